// round 14
// baseline (speedup 1.0000x reference)
#include <cuda_runtime.h>
#include <cuda_fp16.h>
#include <cuda_bf16.h>
#include <math.h>
#include <stdint.h>

// Problem constants
#define BB   2
#define SS   2048
#define DD   2048
#define NH   16
#define NKV  4
#define HD   128
#define EHEADS (NH + 2*NKV)          // 24
#define QKVE (EHEADS * HD)           // 3072

// ---------------- scratch (device globals; no allocation allowed) ----------
__device__ __align__(16) __half g_xh [(size_t)BB*SS*DD];
__device__ __align__(16) __half g_wqh[(size_t)QKVE*DD];
__device__ __align__(16) __nv_bfloat16 g_woh[(size_t)DD*DD];
__device__ __align__(16) __nv_bfloat16 g_wol[(size_t)DD*DD];
__device__ __align__(16) __nv_bfloat16 g_yh [(size_t)BB*SS*DD];
__device__ __align__(16) __nv_bfloat16 g_yl [(size_t)BB*SS*DD];
__device__ __align__(16) __nv_bfloat16 g_qh [(size_t)BB*NH *SS*HD];
__device__ __align__(16) __nv_bfloat16 g_ql [(size_t)BB*NH *SS*HD];
__device__ __align__(16) __nv_bfloat16 g_kh [(size_t)BB*NKV*SS*HD];
__device__ __align__(16) __nv_bfloat16 g_kl [(size_t)BB*NKV*SS*HD];
__device__ __align__(16) __nv_bfloat16 g_vh [(size_t)BB*NKV*SS*HD];
__device__ __align__(16) __nv_bfloat16 g_vl [(size_t)BB*NKV*SS*HD];

// ---------------- helpers ----------------------------------------------------
__device__ __forceinline__ float ex2f(float x) {
    float y;
    asm("ex2.approx.ftz.f32 %0, %1;" : "=f"(y) : "f"(x));
    return y;
}
__device__ __forceinline__ uint32_t s2u(const void* p) {
    uint32_t r;
    asm("{ .reg .u64 t; cvta.to.shared.u64 t, %1; cvt.u32.u64 %0, t; }" : "=r"(r) : "l"(p));
    return r;
}
__device__ __forceinline__ void cp16(uint32_t dst, const void* src) {
    asm volatile("cp.async.cg.shared.global [%0], [%1], 16;" :: "r"(dst), "l"(src));
}
__device__ __forceinline__ uint32_t cvt2(float hi, float lo) {
    uint32_t r;
    asm("cvt.rn.bf16x2.f32 %0, %1, %2;" : "=r"(r) : "f"(hi), "f"(lo));
    return r;
}
__device__ __forceinline__ float lo_f(uint32_t u) { return __uint_as_float(u << 16); }
__device__ __forceinline__ float hi_f(uint32_t u) { return __uint_as_float(u & 0xffff0000u); }
__device__ __forceinline__ uint32_t pack_h2(float lo, float hi) {
    __half2 h = __floats2half2_rn(lo, hi);
    return *reinterpret_cast<uint32_t*>(&h);
}

#define LDSM4(r, addr) \
    asm volatile("ldmatrix.sync.aligned.m8n8.x4.shared.b16 {%0,%1,%2,%3}, [%4];" \
        : "=r"((r)[0]), "=r"((r)[1]), "=r"((r)[2]), "=r"((r)[3]) : "r"(addr))
#define LDSM4T(r, addr) \
    asm volatile("ldmatrix.sync.aligned.m8n8.x4.trans.shared.b16 {%0,%1,%2,%3}, [%4];" \
        : "=r"((r)[0]), "=r"((r)[1]), "=r"((r)[2]), "=r"((r)[3]) : "r"(addr))

#define MMA_BF16(d, a, b0v, b1v) \
    asm volatile("mma.sync.aligned.m16n8k16.row.col.f32.bf16.bf16.f32 " \
        "{%0,%1,%2,%3}, {%4,%5,%6,%7}, {%8,%9}, {%0,%1,%2,%3};" \
        : "+f"((d)[0]), "+f"((d)[1]), "+f"((d)[2]), "+f"((d)[3]) \
        : "r"((a)[0]), "r"((a)[1]), "r"((a)[2]), "r"((a)[3]), "r"(b0v), "r"(b1v))
#define MMA_F16(d, a, b0v, b1v) \
    asm volatile("mma.sync.aligned.m16n8k16.row.col.f32.f16.f16.f32 " \
        "{%0,%1,%2,%3}, {%4,%5,%6,%7}, {%8,%9}, {%0,%1,%2,%3};" \
        : "+f"((d)[0]), "+f"((d)[1]), "+f"((d)[2]), "+f"((d)[3]) \
        : "r"((a)[0]), "r"((a)[1]), "r"((a)[2]), "r"((a)[3]), "r"(b0v), "r"(b1v))

// ---------------- converters --------------------------------------------------
__global__ void __launch_bounds__(256) to_half(const float4* __restrict__ src,
                                               uint2* __restrict__ dst, int n4)
{
    int i = blockIdx.x * 256 + threadIdx.x;
    if (i >= n4) return;
    float4 v = src[i];
    dst[i] = make_uint2(pack_h2(v.x, v.y), pack_h2(v.z, v.w));
}

__global__ void __launch_bounds__(256) split_bf16(const float4* __restrict__ src,
                                                  uint2* __restrict__ hi,
                                                  uint2* __restrict__ lo,
                                                  int n4)
{
    int i = blockIdx.x * 256 + threadIdx.x;
    if (i >= n4) return;
    float4 v = src[i];
    uint32_t h01 = cvt2(v.y, v.x);
    uint32_t h23 = cvt2(v.w, v.z);
    uint32_t l01 = cvt2(v.y - hi_f(h01), v.x - lo_f(h01));
    uint32_t l23 = cvt2(v.w - hi_f(h23), v.z - lo_f(h23));
    hi[i] = make_uint2(h01, h23);
    lo[i] = make_uint2(l01, l23);
}

// ---------------- fused QKV GEMM + RMSNorm + RoPE + bf16 split ---------------
#define QSCALE 0.12751943f   // (1/sqrt(128)) * log2(e)
#define HSTG   10240
#define HSTAGE (2*HSTG)
#define HGSMEM (3*HSTAGE)            // 61440

__global__ void __launch_bounds__(256) gemm_qkv(
    const __half* __restrict__ Ah, const __half* __restrict__ Bh,
    const float* __restrict__ freqs,
    const float* __restrict__ qw, const float* __restrict__ kw,
    __nv_bfloat16* __restrict__ qh, __nv_bfloat16* __restrict__ ql,
    __nv_bfloat16* __restrict__ kh, __nv_bfloat16* __restrict__ kl,
    __nv_bfloat16* __restrict__ vh, __nv_bfloat16* __restrict__ vl)
{
    const int K = DD;
    extern __shared__ __align__(16) char smg[];
    const uint32_t sb = s2u(smg);
    const int tid  = threadIdx.x;
    const int lane = tid & 31;
    const int wid  = tid >> 5;
    const int wr   = wid >> 2;
    const int wc   = wid & 3;
    const int h    = blockIdx.x;
    const int bm   = blockIdx.y << 7;
    const int bn   = h << 7;
    const int nk   = K >> 5;

    float acc[4][4][4];
    #pragma unroll
    for (int i = 0; i < 4; i++)
        #pragma unroll
        for (int j = 0; j < 4; j++)
            #pragma unroll
            for (int r = 0; r < 4; r++) acc[i][j][r] = 0.f;

    const int l8     = lane & 7;
    const int rowA   = ((lane >> 3) & 1) * 8 + l8;
    const int kbyteA = ((lane >> 4) & 1) * 16;
    const int rowB   = ((lane >> 4) & 1) * 8 + l8;
    const int byteB  = ((lane >> 3) & 1) * 16;

    auto fill = [&](int s, int kc) {
        const int k0 = kc << 5;
        const uint32_t dst = sb + s * HSTAGE;
        #pragma unroll
        for (int i = 0; i < 2; i++) {
            int lin = tid + i * 256;
            int row = lin >> 2;
            int ch  = lin & 3;
            uint32_t so = row * 80 + ch * 16;
            cp16(dst +        so, Ah + (size_t)(bm + row) * K + k0 + ch * 8);
            cp16(dst + HSTG + so, Bh + (size_t)(bn + row) * K + k0 + ch * 8);
        }
        asm volatile("cp.async.commit_group;" ::: "memory");
    };

    fill(0, 0);
    fill(1, 1);

    for (int t = 0; t < nk; ++t) {
        if (t + 1 < nk) asm volatile("cp.async.wait_group 1;" ::: "memory");
        else            asm volatile("cp.async.wait_group 0;" ::: "memory");
        __syncthreads();

        if (t + 2 < nk) fill((t + 2) % 3, t + 2);

        const uint32_t st = sb + (t % 3) * HSTAGE;
        #pragma unroll
        for (int kh2 = 0; kh2 < 2; kh2++) {
            uint32_t ah[4][4];
            #pragma unroll
            for (int mi = 0; mi < 4; mi++) {
                uint32_t aaddr = st + (uint32_t)(wr*64 + mi*16 + rowA) * 80
                               + kh2*32 + kbyteA;
                LDSM4(ah[mi], aaddr);
            }
            #pragma unroll
            for (int np = 0; np < 2; np++) {
                uint32_t baddr = st + HSTG + (uint32_t)(wc*32 + np*16 + rowB) * 80
                               + kh2*32 + byteB;
                uint32_t bh4[4];
                LDSM4(bh4, baddr);
                #pragma unroll
                for (int mi = 0; mi < 4; mi++) {
                    MMA_F16(acc[mi][2*np],   ah[mi], bh4[0], bh4[1]);
                    MMA_F16(acc[mi][2*np+1], ah[mi], bh4[2], bh4[3]);
                }
            }
        }
    }

    // ---- fused epilogue: rmsnorm + rope + bf16 split ----
    __syncthreads();
    float* red = (float*)smg;
    const int er = lane >> 2;
    const int ec = (lane & 3) * 2;
    const bool isq = (h < NH);
    const bool isv = (h >= NH + NKV);

    #pragma unroll
    for (int mi = 0; mi < 4; mi++) {
        float s0 = 0.f, s1 = 0.f;
        #pragma unroll
        for (int nn = 0; nn < 4; nn++) {
            s0 += acc[mi][nn][0]*acc[mi][nn][0] + acc[mi][nn][1]*acc[mi][nn][1];
            s1 += acc[mi][nn][2]*acc[mi][nn][2] + acc[mi][nn][3]*acc[mi][nn][3];
        }
        s0 += __shfl_xor_sync(0xffffffffu, s0, 1);
        s0 += __shfl_xor_sync(0xffffffffu, s0, 2);
        s1 += __shfl_xor_sync(0xffffffffu, s1, 1);
        s1 += __shfl_xor_sync(0xffffffffu, s1, 2);
        if ((lane & 3) == 0) {
            red[(wr*64 + mi*16 + er)     * 4 + wc] = s0;
            red[(wr*64 + mi*16 + er + 8) * 4 + wc] = s1;
        }
    }
    __syncthreads();

    const float* wn = isq ? qw : kw;
    const float fold = isq ? QSCALE : 1.0f;

    #pragma unroll
    for (int mi = 0; mi < 4; mi++) {
        #pragma unroll
        for (int half = 0; half < 2; half++) {
            const int row = wr*64 + mi*16 + er + half*8;
            const int n   = bm + row;
            const int b   = n >> 11;
            const int s   = n & 2047;
            float inv = 1.0f;
            if (!isv) {
                float ssq = red[row*4+0] + red[row*4+1] + red[row*4+2] + red[row*4+3];
                inv = rsqrtf(ssq * (1.0f / HD) + 1e-6f) * fold;
            }
            size_t drow;
            __nv_bfloat16 *dh, *dl;
            if (isq)      { drow = (size_t)(b*NH  + h)          * SS + s; dh = qh; dl = ql; }
            else if (!isv){ drow = (size_t)(b*NKV + h - NH)     * SS + s; dh = kh; dl = kl; }
            else          { drow = (size_t)(b*NKV + h - NH - NKV)* SS + s; dh = vh; dl = vl; }

            #pragma unroll
            for (int nn = 0; nn < 4; nn++) {
                const int col = wc*32 + nn*8 + ec;
                float v0 = acc[mi][nn][half*2];
                float v1 = acc[mi][nn][half*2+1];
                float o0, o1;
                if (!isv) {
                    float2 wv = *(const float2*)(wn + col);
                    float2 f  = *(const float2*)(freqs + (size_t)s*128 + col);
                    float x0 = v0 * inv * wv.x;
                    float x1 = v1 * inv * wv.y;
                    o0 = x0*f.x - x1*f.y;
                    o1 = x1*f.x + x0*f.y;
                } else {
                    o0 = v0; o1 = v1;
                }
                uint32_t hp = cvt2(o1, o0);
                uint32_t lp = cvt2(o1 - hi_f(hp), o0 - lo_f(hp));
                *(uint32_t*)(dh + drow*HD + col) = hp;
                *(uint32_t*)(dl + drow*HD + col) = lp;
            }
        }
    }
}

// ---------------- bf16x3 GEMM: 64x64 warp tiles, 1 sync/chunk ---------------
// CTA 128x128, 4 warps, 2-stage. MMA:LDSM = 6:1 per kh block.
#define STG   10240
#define STAGE (4*STG)
#define GSMEM (2*STAGE)              // 81920

__global__ void __launch_bounds__(128) gemm_mma3(
    const __nv_bfloat16* __restrict__ Ah, const __nv_bfloat16* __restrict__ Al,
    const __nv_bfloat16* __restrict__ Bh, const __nv_bfloat16* __restrict__ Bl,
    float* __restrict__ C, int N, int K)
{
    extern __shared__ __align__(16) char smg[];
    const uint32_t sb = s2u(smg);
    const int tid  = threadIdx.x;
    const int lane = tid & 31;
    const int wid  = tid >> 5;           // 0..3
    const int wr   = wid >> 1;           // 0..1 (64-row slab)
    const int wc   = wid & 1;            // 0..1 (64-col slab)
    const int bm   = blockIdx.y << 7;
    const int bn   = blockIdx.x << 7;
    const int nk   = K >> 5;

    float acc[4][8][4];
    #pragma unroll
    for (int i = 0; i < 4; i++)
        #pragma unroll
        for (int j = 0; j < 8; j++)
            #pragma unroll
            for (int r = 0; r < 4; r++) acc[i][j][r] = 0.f;

    const int l8     = lane & 7;
    const int rowA   = ((lane >> 3) & 1) * 8 + l8;
    const int kbyteA = ((lane >> 4) & 1) * 16;
    const int rowB   = ((lane >> 4) & 1) * 8 + l8;
    const int byteB  = ((lane >> 3) & 1) * 16;

    auto fill = [&](int s, int kc) {
        const int k0 = kc << 5;
        const uint32_t dst = sb + s * STAGE;
        #pragma unroll
        for (int i = 0; i < 4; i++) {
            int lin = tid + i * 128;
            int row = lin >> 2;
            int ch  = lin & 3;
            uint32_t so = row * 80 + ch * 16;
            size_t ga = (size_t)(bm + row) * K + k0 + ch * 8;
            size_t gb = (size_t)(bn + row) * K + k0 + ch * 8;
            cp16(dst +           so, Ah + ga);
            cp16(dst + STG     + so, Al + ga);
            cp16(dst + 2*STG   + so, Bh + gb);
            cp16(dst + 3*STG   + so, Bl + gb);
        }
        asm volatile("cp.async.commit_group;" ::: "memory");
    };

    fill(0, 0);

    for (int t = 0; t < nk; ++t) {
        asm volatile("cp.async.wait_group 0;" ::: "memory");   // fill(t) done
        __syncthreads();                                       // compute(t-1) done by all
        if (t + 1 < nk) fill((t + 1) & 1, t + 1);              // overwrites stage of compute(t-1)

        const uint32_t st = sb + (t & 1) * STAGE;
        #pragma unroll
        for (int kh = 0; kh < 2; kh++) {
            uint32_t ah[4][4], al[4][4];
            #pragma unroll
            for (int mi = 0; mi < 4; mi++) {
                uint32_t aaddr = st + (uint32_t)(wr*64 + mi*16 + rowA) * 80
                               + kh*32 + kbyteA;
                LDSM4(ah[mi], aaddr);
                LDSM4(al[mi], aaddr + STG);
            }
            #pragma unroll
            for (int np = 0; np < 4; np++) {
                uint32_t baddr = st + 2*STG + (uint32_t)(wc*64 + np*16 + rowB) * 80
                               + kh*32 + byteB;
                uint32_t bh[4], bl[4];
                LDSM4(bh, baddr);
                LDSM4(bl, baddr + STG);
                #pragma unroll
                for (int mi = 0; mi < 4; mi++) {
                    MMA_BF16(acc[mi][2*np],   ah[mi], bh[0], bh[1]);
                    MMA_BF16(acc[mi][2*np],   ah[mi], bl[0], bl[1]);
                    MMA_BF16(acc[mi][2*np],   al[mi], bh[0], bh[1]);
                    MMA_BF16(acc[mi][2*np+1], ah[mi], bh[2], bh[3]);
                    MMA_BF16(acc[mi][2*np+1], ah[mi], bl[2], bl[3]);
                    MMA_BF16(acc[mi][2*np+1], al[mi], bh[2], bh[3]);
                }
            }
        }
    }

    const int er = lane >> 2;
    const int ec = (lane & 3) * 2;
    #pragma unroll
    for (int mi = 0; mi < 4; mi++) {
        #pragma unroll
        for (int nn = 0; nn < 8; nn++) {
            float* cp0 = C + (size_t)(bm + wr*64 + mi*16 + er) * N
                           + bn + wc*64 + nn*8 + ec;
            *(float2*)cp0         = make_float2(acc[mi][nn][0], acc[mi][nn][1]);
            *(float2*)(cp0 + 8*N) = make_float2(acc[mi][nn][2], acc[mi][nn][3]);
        }
    }
}

// ---------------- Flash attention (bf16x3), BM=64, 4 warps, 2 CTAs/SM --------
#define FST 272
#define Q_OFF  0
#define QL_OFF (64*FST)
#define KH_OFF (2*64*FST)
#define KL_OFF (3*64*FST)
#define VH_OFF (4*64*FST)
#define VL_OFF (5*64*FST)
#define FLASH_SMEM (6*64*FST)           // 104448

__global__ void __launch_bounds__(128) flash_mma(
    const __nv_bfloat16* __restrict__ qh, const __nv_bfloat16* __restrict__ ql,
    const __nv_bfloat16* __restrict__ kh, const __nv_bfloat16* __restrict__ kl,
    const __nv_bfloat16* __restrict__ vh, const __nv_bfloat16* __restrict__ vl,
    __nv_bfloat16* __restrict__ Yh, __nv_bfloat16* __restrict__ Yl)
{
    extern __shared__ __align__(16) char smf[];
    const uint32_t sb = s2u(smf);
    const int tid  = threadIdx.x;
    const int lane = tid & 31;
    const int wid  = tid >> 5;
    const int qb   = gridDim.x - 1 - blockIdx.x;
    const int h    = blockIdx.y;
    const int b    = blockIdx.z;
    const int q0   = qb * 64;
    const int hkv  = h >> 2;
    const int mrow = wid * 16;

    const __nv_bfloat16* qhp = qh + ((size_t)(b*NH  + h  ) * SS + q0) * HD;
    const __nv_bfloat16* qlp = ql + ((size_t)(b*NH  + h  ) * SS + q0) * HD;
    const __nv_bfloat16* khp = kh + ((size_t)(b*NKV + hkv) * SS) * HD;
    const __nv_bfloat16* klp = kl + ((size_t)(b*NKV + hkv) * SS) * HD;
    const __nv_bfloat16* vhp = vh + ((size_t)(b*NKV + hkv) * SS) * HD;
    const __nv_bfloat16* vlp = vl + ((size_t)(b*NKV + hkv) * SS) * HD;

    #pragma unroll
    for (int i = 0; i < 8; i++) {
        int lin = tid + i*128;
        int r   = lin >> 4;
        int ch  = lin & 15;
        cp16(sb + Q_OFF  + r*FST + ch*16, qhp + (size_t)r*HD + ch*8);
        cp16(sb + QL_OFF + r*FST + ch*16, qlp + (size_t)r*HD + ch*8);
    }
    asm volatile("cp.async.commit_group;" ::: "memory");

    const int l8 = lane & 7;
    const int rA = ((lane >> 3) & 1) * 8 + l8;
    const int cA = ((lane >> 4) & 1) * 16;
    const int rB = ((lane >> 4) & 1) * 8 + l8;
    const int cB = ((lane >> 3) & 1) * 16;
    const int lr = lane >> 2;
    const int l4 = lane & 3;

    float O[16][4];
    #pragma unroll
    for (int j = 0; j < 16; j++)
        #pragma unroll
        for (int r = 0; r < 4; r++) O[j][r] = 0.f;
    float m0v = -1e30f, m1v = -1e30f, l0v = 0.f, l1v = 0.f;

    const int nkb = qb + 1;
    for (int kb = 0; kb < nkb; ++kb) {
        const int k0 = kb * 64;
        if (kb) __syncthreads();
        #pragma unroll
        for (int i = 0; i < 8; i++) {
            int lin = tid + i*128;
            int r   = lin >> 4;
            int ch  = lin & 15;
            size_t g = (size_t)(k0 + r)*HD + ch*8;
            uint32_t so = r*FST + ch*16;
            cp16(sb + KH_OFF + so, khp + g);
            cp16(sb + KL_OFF + so, klp + g);
            cp16(sb + VH_OFF + so, vhp + g);
            cp16(sb + VL_OFF + so, vlp + g);
        }
        asm volatile("cp.async.commit_group;" ::: "memory");
        asm volatile("cp.async.wait_group 0;" ::: "memory");
        __syncthreads();

        float S[8][4];
        #pragma unroll
        for (int j = 0; j < 8; j++)
            #pragma unroll
            for (int r = 0; r < 4; r++) S[j][r] = 0.f;

        #pragma unroll
        for (int kc = 0; kc < 8; kc++) {
            uint32_t qa_h[4], qa_l[4];
            uint32_t qaddr = sb + Q_OFF + (uint32_t)(mrow + rA)*FST + kc*32 + cA;
            LDSM4(qa_h, qaddr);
            LDSM4(qa_l, qaddr + QL_OFF);
            #pragma unroll
            for (int ng = 0; ng < 4; ng++) {
                uint32_t kaddr = sb + KH_OFF + (uint32_t)(ng*16 + rB)*FST + kc*32 + cB;
                uint32_t bh4[4], bl4[4];
                LDSM4(bh4, kaddr);
                LDSM4(bl4, kaddr + (KL_OFF - KH_OFF));
                MMA_BF16(S[2*ng],   qa_h, bh4[0], bh4[1]);
                MMA_BF16(S[2*ng],   qa_h, bl4[0], bl4[1]);
                MMA_BF16(S[2*ng],   qa_l, bh4[0], bh4[1]);
                MMA_BF16(S[2*ng+1], qa_h, bh4[2], bh4[3]);
                MMA_BF16(S[2*ng+1], qa_h, bl4[2], bl4[3]);
                MMA_BF16(S[2*ng+1], qa_l, bh4[2], bh4[3]);
            }
        }

        if (kb == qb) {
            int row0 = q0 + mrow + lr;
            int row1 = row0 + 8;
            #pragma unroll
            for (int j = 0; j < 8; j++) {
                int c0 = k0 + 8*j + 2*l4;
                if (c0     > row0) S[j][0] = -1e30f;
                if (c0 + 1 > row0) S[j][1] = -1e30f;
                if (c0     > row1) S[j][2] = -1e30f;
                if (c0 + 1 > row1) S[j][3] = -1e30f;
            }
        }

        {
            float mx = -1e30f;
            #pragma unroll
            for (int j = 0; j < 8; j++) mx = fmaxf(mx, fmaxf(S[j][0], S[j][1]));
            mx = fmaxf(mx, __shfl_xor_sync(0xffffffffu, mx, 1));
            mx = fmaxf(mx, __shfl_xor_sync(0xffffffffu, mx, 2));
            float mn = fmaxf(m0v, mx);
            float corr = ex2f(m0v - mn);
            m0v = mn;
            float rs = 0.f;
            #pragma unroll
            for (int j = 0; j < 8; j++) {
                S[j][0] = ex2f(S[j][0] - mn);
                S[j][1] = ex2f(S[j][1] - mn);
                rs += S[j][0] + S[j][1];
            }
            rs += __shfl_xor_sync(0xffffffffu, rs, 1);
            rs += __shfl_xor_sync(0xffffffffu, rs, 2);
            l0v = l0v * corr + rs;
            #pragma unroll
            for (int j = 0; j < 16; j++) { O[j][0] *= corr; O[j][1] *= corr; }
        }
        {
            float mx = -1e30f;
            #pragma unroll
            for (int j = 0; j < 8; j++) mx = fmaxf(mx, fmaxf(S[j][2], S[j][3]));
            mx = fmaxf(mx, __shfl_xor_sync(0xffffffffu, mx, 1));
            mx = fmaxf(mx, __shfl_xor_sync(0xffffffffu, mx, 2));
            float mn = fmaxf(m1v, mx);
            float corr = ex2f(m1v - mn);
            m1v = mn;
            float rs = 0.f;
            #pragma unroll
            for (int j = 0; j < 8; j++) {
                S[j][2] = ex2f(S[j][2] - mn);
                S[j][3] = ex2f(S[j][3] - mn);
                rs += S[j][2] + S[j][3];
            }
            rs += __shfl_xor_sync(0xffffffffu, rs, 1);
            rs += __shfl_xor_sync(0xffffffffu, rs, 2);
            l1v = l1v * corr + rs;
            #pragma unroll
            for (int j = 0; j < 16; j++) { O[j][2] *= corr; O[j][3] *= corr; }
        }

        #pragma unroll
        for (int t = 0; t < 4; t++) {
            uint32_t Ahf[4], Alf[4];
            Ahf[0] = cvt2(S[2*t][1],   S[2*t][0]);
            Ahf[1] = cvt2(S[2*t][3],   S[2*t][2]);
            Ahf[2] = cvt2(S[2*t+1][1], S[2*t+1][0]);
            Ahf[3] = cvt2(S[2*t+1][3], S[2*t+1][2]);
            Alf[0] = cvt2(S[2*t][1]   - hi_f(Ahf[0]), S[2*t][0]   - lo_f(Ahf[0]));
            Alf[1] = cvt2(S[2*t][3]   - hi_f(Ahf[1]), S[2*t][2]   - lo_f(Ahf[1]));
            Alf[2] = cvt2(S[2*t+1][1] - hi_f(Ahf[2]), S[2*t+1][0] - lo_f(Ahf[2]));
            Alf[3] = cvt2(S[2*t+1][3] - hi_f(Ahf[3]), S[2*t+1][2] - lo_f(Ahf[3]));
            #pragma unroll
            for (int dg = 0; dg < 8; dg++) {
                uint32_t vaddr = sb + VH_OFF + (uint32_t)(t*16 + rA)*FST + dg*32 + cA;
                uint32_t vhf[4], vlf[4];
                LDSM4T(vhf, vaddr);
                LDSM4T(vlf, vaddr + (VL_OFF - VH_OFF));
                MMA_BF16(O[2*dg],   Ahf, vhf[0], vhf[1]);
                MMA_BF16(O[2*dg],   Ahf, vlf[0], vlf[1]);
                MMA_BF16(O[2*dg],   Alf, vhf[0], vhf[1]);
                MMA_BF16(O[2*dg+1], Ahf, vhf[2], vhf[3]);
                MMA_BF16(O[2*dg+1], Ahf, vlf[2], vlf[3]);
                MMA_BF16(O[2*dg+1], Alf, vhf[2], vhf[3]);
            }
        }
    }

    float inv0 = 1.0f / l0v;
    float inv1 = 1.0f / l1v;
    int row0 = q0 + mrow + lr;
    size_t base0 = (size_t)(b*SS + row0) * DD + h*HD;
    size_t base1 = base0 + (size_t)8 * DD;
    #pragma unroll
    for (int j = 0; j < 16; j++) {
        float a0 = O[j][0]*inv0, a1 = O[j][1]*inv0;
        float b0 = O[j][2]*inv1, b1 = O[j][3]*inv1;
        uint32_t h0 = cvt2(a1, a0);
        uint32_t l0 = cvt2(a1 - hi_f(h0), a0 - lo_f(h0));
        uint32_t h1 = cvt2(b1, b0);
        uint32_t l1 = cvt2(b1 - hi_f(h1), b0 - lo_f(h1));
        *(uint32_t*)(Yh + base0 + 8*j + 2*l4) = h0;
        *(uint32_t*)(Yl + base0 + 8*j + 2*l4) = l0;
        *(uint32_t*)(Yh + base1 + 8*j + 2*l4) = h1;
        *(uint32_t*)(Yl + base1 + 8*j + 2*l4) = l1;
    }
}

// ---------------- launch ----------------------------------------------------
extern "C" void kernel_launch(void* const* d_in, const int* in_sizes, int n_in,
                              void* d_out, int out_size)
{
    const float* x     = (const float*)d_in[0];
    const float* freqs = (const float*)d_in[1];
    const float* wqkv  = (const float*)d_in[2];
    const float* wo    = (const float*)d_in[3];
    const float* qw    = (const float*)d_in[4];
    const float* kw    = (const float*)d_in[5];
    float* out = (float*)d_out;

    __half *p_xh, *p_wqh;
    __nv_bfloat16 *p_woh, *p_wol, *p_yh, *p_yl;
    __nv_bfloat16 *p_qh, *p_ql, *p_kh, *p_kl, *p_vh, *p_vl;
    cudaGetSymbolAddress((void**)&p_xh,  g_xh);
    cudaGetSymbolAddress((void**)&p_wqh, g_wqh);
    cudaGetSymbolAddress((void**)&p_woh, g_woh);
    cudaGetSymbolAddress((void**)&p_wol, g_wol);
    cudaGetSymbolAddress((void**)&p_yh,  g_yh);
    cudaGetSymbolAddress((void**)&p_yl,  g_yl);
    cudaGetSymbolAddress((void**)&p_qh,  g_qh);
    cudaGetSymbolAddress((void**)&p_ql,  g_ql);
    cudaGetSymbolAddress((void**)&p_kh,  g_kh);
    cudaGetSymbolAddress((void**)&p_kl,  g_kl);
    cudaGetSymbolAddress((void**)&p_vh,  g_vh);
    cudaGetSymbolAddress((void**)&p_vl,  g_vl);

    cudaFuncSetAttribute(gemm_qkv,
                         cudaFuncAttributeMaxDynamicSharedMemorySize, HGSMEM);
    cudaFuncSetAttribute(gemm_mma3,
                         cudaFuncAttributeMaxDynamicSharedMemorySize, GSMEM);
    cudaFuncSetAttribute(flash_mma,
                         cudaFuncAttributeMaxDynamicSharedMemorySize, FLASH_SMEM);

    const int n4_x  = BB*SS*DD / 4;
    const int n4_wq = QKVE*DD  / 4;
    const int n4_wo = DD*DD    / 4;

    // 0) converts
    to_half<<<n4_x /256, 256>>>((const float4*)x,    (uint2*)p_xh,  n4_x);
    to_half<<<n4_wq/256, 256>>>((const float4*)wqkv, (uint2*)p_wqh, n4_wq);
    split_bf16<<<n4_wo/256, 256>>>((const float4*)wo, (uint2*)p_woh, (uint2*)p_wol, n4_wo);

    // 1) fused QKV projection + RMSNorm + RoPE + bf16 split
    gemm_qkv<<<dim3(EHEADS, (BB*SS)/128), 256, HGSMEM>>>(
        p_xh, p_wqh, freqs, qw, kw,
        p_qh, p_ql, p_kh, p_kl, p_vh, p_vl);

    // 2) Flash attention (bf16x3)
    flash_mma<<<dim3(SS/64, NH, BB), 128, FLASH_SMEM>>>(
        p_qh, p_ql, p_kh, p_kl, p_vh, p_vl, p_yh, p_yl);

    // 3) Output projection (bf16x3, 64x64 warp tiles, 1-sync pipeline)
    gemm_mma3<<<dim3(DD/128, (BB*SS)/128), 128, GSMEM>>>(
        p_yh, p_yl, p_woh, p_wol, out, DD, NH*HD);
}

// round 15
// speedup vs baseline: 1.1366x; 1.1366x over previous
#include <cuda_runtime.h>
#include <cuda_fp16.h>
#include <cuda_bf16.h>
#include <math.h>
#include <stdint.h>

// Problem constants
#define BB   2
#define SS   2048
#define DD   2048
#define NH   16
#define NKV  4
#define HD   128
#define EHEADS (NH + 2*NKV)          // 24
#define QKVE (EHEADS * HD)           // 3072

// ---------------- scratch (device globals; no allocation allowed) ----------
__device__ __align__(16) __half g_xh [(size_t)BB*SS*DD];
__device__ __align__(16) __half g_wqh[(size_t)QKVE*DD];
__device__ __align__(16) __half g_woh[(size_t)DD*DD];          // wo fp16 (single)
__device__ __align__(16) __half g_yh [(size_t)BB*SS*DD];       // y fp16 hi
__device__ __align__(16) __half g_yl [(size_t)BB*SS*DD];       // y fp16 lo (residual)
__device__ __align__(16) __nv_bfloat16 g_qh [(size_t)BB*NH *SS*HD];
__device__ __align__(16) __nv_bfloat16 g_ql [(size_t)BB*NH *SS*HD];
__device__ __align__(16) __nv_bfloat16 g_kh [(size_t)BB*NKV*SS*HD];
__device__ __align__(16) __nv_bfloat16 g_kl [(size_t)BB*NKV*SS*HD];
__device__ __align__(16) __nv_bfloat16 g_vh [(size_t)BB*NKV*SS*HD];
__device__ __align__(16) __nv_bfloat16 g_vl [(size_t)BB*NKV*SS*HD];

// ---------------- helpers ----------------------------------------------------
__device__ __forceinline__ float ex2f(float x) {
    float y;
    asm("ex2.approx.ftz.f32 %0, %1;" : "=f"(y) : "f"(x));
    return y;
}
__device__ __forceinline__ uint32_t s2u(const void* p) {
    uint32_t r;
    asm("{ .reg .u64 t; cvta.to.shared.u64 t, %1; cvt.u32.u64 %0, t; }" : "=r"(r) : "l"(p));
    return r;
}
__device__ __forceinline__ void cp16(uint32_t dst, const void* src) {
    asm volatile("cp.async.cg.shared.global [%0], [%1], 16;" :: "r"(dst), "l"(src));
}
__device__ __forceinline__ uint32_t cvt2(float hi, float lo) {
    uint32_t r;
    asm("cvt.rn.bf16x2.f32 %0, %1, %2;" : "=r"(r) : "f"(hi), "f"(lo));
    return r;
}
__device__ __forceinline__ float lo_f(uint32_t u) { return __uint_as_float(u << 16); }
__device__ __forceinline__ float hi_f(uint32_t u) { return __uint_as_float(u & 0xffff0000u); }
__device__ __forceinline__ uint32_t pack_h2(float lo, float hi) {
    __half2 h = __floats2half2_rn(lo, hi);
    return *reinterpret_cast<uint32_t*>(&h);
}
__device__ __forceinline__ float h2lo(uint32_t u) {
    __half2 h = *reinterpret_cast<__half2*>(&u);
    return __low2float(h);
}
__device__ __forceinline__ float h2hi(uint32_t u) {
    __half2 h = *reinterpret_cast<__half2*>(&u);
    return __high2float(h);
}

#define LDSM4(r, addr) \
    asm volatile("ldmatrix.sync.aligned.m8n8.x4.shared.b16 {%0,%1,%2,%3}, [%4];" \
        : "=r"((r)[0]), "=r"((r)[1]), "=r"((r)[2]), "=r"((r)[3]) : "r"(addr))
#define LDSM4T(r, addr) \
    asm volatile("ldmatrix.sync.aligned.m8n8.x4.trans.shared.b16 {%0,%1,%2,%3}, [%4];" \
        : "=r"((r)[0]), "=r"((r)[1]), "=r"((r)[2]), "=r"((r)[3]) : "r"(addr))

#define MMA_BF16(d, a, b0v, b1v) \
    asm volatile("mma.sync.aligned.m16n8k16.row.col.f32.bf16.bf16.f32 " \
        "{%0,%1,%2,%3}, {%4,%5,%6,%7}, {%8,%9}, {%0,%1,%2,%3};" \
        : "+f"((d)[0]), "+f"((d)[1]), "+f"((d)[2]), "+f"((d)[3]) \
        : "r"((a)[0]), "r"((a)[1]), "r"((a)[2]), "r"((a)[3]), "r"(b0v), "r"(b1v))
#define MMA_F16(d, a, b0v, b1v) \
    asm volatile("mma.sync.aligned.m16n8k16.row.col.f32.f16.f16.f32 " \
        "{%0,%1,%2,%3}, {%4,%5,%6,%7}, {%8,%9}, {%0,%1,%2,%3};" \
        : "+f"((d)[0]), "+f"((d)[1]), "+f"((d)[2]), "+f"((d)[3]) \
        : "r"((a)[0]), "r"((a)[1]), "r"((a)[2]), "r"((a)[3]), "r"(b0v), "r"(b1v))

// ---------------- converters --------------------------------------------------
__global__ void __launch_bounds__(256) to_half(const float4* __restrict__ src,
                                               uint2* __restrict__ dst, int n4)
{
    int i = blockIdx.x * 256 + threadIdx.x;
    if (i >= n4) return;
    float4 v = src[i];
    dst[i] = make_uint2(pack_h2(v.x, v.y), pack_h2(v.z, v.w));
}

// ---------------- fused QKV GEMM + RMSNorm + RoPE + bf16 split ---------------
#define QSCALE 0.12751943f   // (1/sqrt(128)) * log2(e)
#define HSTG   10240
#define HSTAGE (2*HSTG)
#define HGSMEM (3*HSTAGE)            // 61440

__global__ void __launch_bounds__(256) gemm_qkv(
    const __half* __restrict__ Ah, const __half* __restrict__ Bh,
    const float* __restrict__ freqs,
    const float* __restrict__ qw, const float* __restrict__ kw,
    __nv_bfloat16* __restrict__ qh, __nv_bfloat16* __restrict__ ql,
    __nv_bfloat16* __restrict__ kh, __nv_bfloat16* __restrict__ kl,
    __nv_bfloat16* __restrict__ vh, __nv_bfloat16* __restrict__ vl)
{
    const int K = DD;
    extern __shared__ __align__(16) char smg[];
    const uint32_t sb = s2u(smg);
    const int tid  = threadIdx.x;
    const int lane = tid & 31;
    const int wid  = tid >> 5;
    const int wr   = wid >> 2;
    const int wc   = wid & 3;
    const int h    = blockIdx.x;
    const int bm   = blockIdx.y << 7;
    const int bn   = h << 7;
    const int nk   = K >> 5;

    float acc[4][4][4];
    #pragma unroll
    for (int i = 0; i < 4; i++)
        #pragma unroll
        for (int j = 0; j < 4; j++)
            #pragma unroll
            for (int r = 0; r < 4; r++) acc[i][j][r] = 0.f;

    const int l8     = lane & 7;
    const int rowA   = ((lane >> 3) & 1) * 8 + l8;
    const int kbyteA = ((lane >> 4) & 1) * 16;
    const int rowB   = ((lane >> 4) & 1) * 8 + l8;
    const int byteB  = ((lane >> 3) & 1) * 16;

    auto fill = [&](int s, int kc) {
        const int k0 = kc << 5;
        const uint32_t dst = sb + s * HSTAGE;
        #pragma unroll
        for (int i = 0; i < 2; i++) {
            int lin = tid + i * 256;
            int row = lin >> 2;
            int ch  = lin & 3;
            uint32_t so = row * 80 + ch * 16;
            cp16(dst +        so, Ah + (size_t)(bm + row) * K + k0 + ch * 8);
            cp16(dst + HSTG + so, Bh + (size_t)(bn + row) * K + k0 + ch * 8);
        }
        asm volatile("cp.async.commit_group;" ::: "memory");
    };

    fill(0, 0);
    fill(1, 1);

    for (int t = 0; t < nk; ++t) {
        if (t + 1 < nk) asm volatile("cp.async.wait_group 1;" ::: "memory");
        else            asm volatile("cp.async.wait_group 0;" ::: "memory");
        __syncthreads();

        if (t + 2 < nk) fill((t + 2) % 3, t + 2);

        const uint32_t st = sb + (t % 3) * HSTAGE;
        #pragma unroll
        for (int kh2 = 0; kh2 < 2; kh2++) {
            uint32_t ah[4][4];
            #pragma unroll
            for (int mi = 0; mi < 4; mi++) {
                uint32_t aaddr = st + (uint32_t)(wr*64 + mi*16 + rowA) * 80
                               + kh2*32 + kbyteA;
                LDSM4(ah[mi], aaddr);
            }
            #pragma unroll
            for (int np = 0; np < 2; np++) {
                uint32_t baddr = st + HSTG + (uint32_t)(wc*32 + np*16 + rowB) * 80
                               + kh2*32 + byteB;
                uint32_t bh4[4];
                LDSM4(bh4, baddr);
                #pragma unroll
                for (int mi = 0; mi < 4; mi++) {
                    MMA_F16(acc[mi][2*np],   ah[mi], bh4[0], bh4[1]);
                    MMA_F16(acc[mi][2*np+1], ah[mi], bh4[2], bh4[3]);
                }
            }
        }
    }

    // ---- fused epilogue: rmsnorm + rope + bf16 split ----
    __syncthreads();
    float* red = (float*)smg;
    const int er = lane >> 2;
    const int ec = (lane & 3) * 2;
    const bool isq = (h < NH);
    const bool isv = (h >= NH + NKV);

    #pragma unroll
    for (int mi = 0; mi < 4; mi++) {
        float s0 = 0.f, s1 = 0.f;
        #pragma unroll
        for (int nn = 0; nn < 4; nn++) {
            s0 += acc[mi][nn][0]*acc[mi][nn][0] + acc[mi][nn][1]*acc[mi][nn][1];
            s1 += acc[mi][nn][2]*acc[mi][nn][2] + acc[mi][nn][3]*acc[mi][nn][3];
        }
        s0 += __shfl_xor_sync(0xffffffffu, s0, 1);
        s0 += __shfl_xor_sync(0xffffffffu, s0, 2);
        s1 += __shfl_xor_sync(0xffffffffu, s1, 1);
        s1 += __shfl_xor_sync(0xffffffffu, s1, 2);
        if ((lane & 3) == 0) {
            red[(wr*64 + mi*16 + er)     * 4 + wc] = s0;
            red[(wr*64 + mi*16 + er + 8) * 4 + wc] = s1;
        }
    }
    __syncthreads();

    const float* wn = isq ? qw : kw;
    const float fold = isq ? QSCALE : 1.0f;

    #pragma unroll
    for (int mi = 0; mi < 4; mi++) {
        #pragma unroll
        for (int half = 0; half < 2; half++) {
            const int row = wr*64 + mi*16 + er + half*8;
            const int n   = bm + row;
            const int b   = n >> 11;
            const int s   = n & 2047;
            float inv = 1.0f;
            if (!isv) {
                float ssq = red[row*4+0] + red[row*4+1] + red[row*4+2] + red[row*4+3];
                inv = rsqrtf(ssq * (1.0f / HD) + 1e-6f) * fold;
            }
            size_t drow;
            __nv_bfloat16 *dh, *dl;
            if (isq)      { drow = (size_t)(b*NH  + h)          * SS + s; dh = qh; dl = ql; }
            else if (!isv){ drow = (size_t)(b*NKV + h - NH)     * SS + s; dh = kh; dl = kl; }
            else          { drow = (size_t)(b*NKV + h - NH - NKV)* SS + s; dh = vh; dl = vl; }

            #pragma unroll
            for (int nn = 0; nn < 4; nn++) {
                const int col = wc*32 + nn*8 + ec;
                float v0 = acc[mi][nn][half*2];
                float v1 = acc[mi][nn][half*2+1];
                float o0, o1;
                if (!isv) {
                    float2 wv = *(const float2*)(wn + col);
                    float2 f  = *(const float2*)(freqs + (size_t)s*128 + col);
                    float x0 = v0 * inv * wv.x;
                    float x1 = v1 * inv * wv.y;
                    o0 = x0*f.x - x1*f.y;
                    o1 = x1*f.x + x0*f.y;
                } else {
                    o0 = v0; o1 = v1;
                }
                uint32_t hp = cvt2(o1, o0);
                uint32_t lp = cvt2(o1 - hi_f(hp), o0 - lo_f(hp));
                *(uint32_t*)(dh + drow*HD + col) = hp;
                *(uint32_t*)(dl + drow*HD + col) = lp;
            }
        }
    }
}

// ---------------- out-projection GEMM: fp16 2-pass (y exact-split, wo fp16) --
// C[M,N] = (Yh+Yl)[M,K] * Wo[N,K]^T. 256 threads, 64x32 warp tiles,
// 3-stage 1-sync pipeline.
#define OSTG   10240
#define OSTAGE (3*OSTG)              // Ah, Al, Bh
#define OGSMEM (3*OSTAGE)            // 92160

__global__ void __launch_bounds__(256) gemm_out2(
    const __half* __restrict__ Ah, const __half* __restrict__ Al,
    const __half* __restrict__ Bh,
    float* __restrict__ C, int N, int K)
{
    extern __shared__ __align__(16) char smg[];
    const uint32_t sb = s2u(smg);
    const int tid  = threadIdx.x;
    const int lane = tid & 31;
    const int wid  = tid >> 5;
    const int wr   = wid >> 2;
    const int wc   = wid & 3;
    const int bm   = blockIdx.y << 7;
    const int bn   = blockIdx.x << 7;
    const int nk   = K >> 5;

    float acc[4][4][4];
    #pragma unroll
    for (int i = 0; i < 4; i++)
        #pragma unroll
        for (int j = 0; j < 4; j++)
            #pragma unroll
            for (int r = 0; r < 4; r++) acc[i][j][r] = 0.f;

    const int l8     = lane & 7;
    const int rowA   = ((lane >> 3) & 1) * 8 + l8;
    const int kbyteA = ((lane >> 4) & 1) * 16;
    const int rowB   = ((lane >> 4) & 1) * 8 + l8;
    const int byteB  = ((lane >> 3) & 1) * 16;

    auto fill = [&](int s, int kc) {
        const int k0 = kc << 5;
        const uint32_t dst = sb + s * OSTAGE;
        #pragma unroll
        for (int i = 0; i < 2; i++) {
            int lin = tid + i * 256;
            int row = lin >> 2;
            int ch  = lin & 3;
            uint32_t so = row * 80 + ch * 16;
            size_t ga = (size_t)(bm + row) * K + k0 + ch * 8;
            cp16(dst +          so, Ah + ga);
            cp16(dst + OSTG   + so, Al + ga);
            cp16(dst + 2*OSTG + so, Bh + (size_t)(bn + row) * K + k0 + ch * 8);
        }
        asm volatile("cp.async.commit_group;" ::: "memory");
    };

    fill(0, 0);
    if (nk > 1) fill(1, 1);

    for (int t = 0; t < nk; ++t) {
        if (t + 1 < nk) asm volatile("cp.async.wait_group 1;" ::: "memory");
        else            asm volatile("cp.async.wait_group 0;" ::: "memory");
        __syncthreads();

        if (t + 2 < nk) fill((t + 2) % 3, t + 2);

        const uint32_t st = sb + (t % 3) * OSTAGE;
        #pragma unroll
        for (int kh = 0; kh < 2; kh++) {
            uint32_t ah[4][4], al[4][4];
            #pragma unroll
            for (int mi = 0; mi < 4; mi++) {
                uint32_t aaddr = st + (uint32_t)(wr*64 + mi*16 + rowA) * 80
                               + kh*32 + kbyteA;
                LDSM4(ah[mi], aaddr);
                LDSM4(al[mi], aaddr + OSTG);
            }
            #pragma unroll
            for (int np = 0; np < 2; np++) {
                uint32_t baddr = st + 2*OSTG + (uint32_t)(wc*32 + np*16 + rowB) * 80
                               + kh*32 + byteB;
                uint32_t bh4[4];
                LDSM4(bh4, baddr);
                #pragma unroll
                for (int mi = 0; mi < 4; mi++) {
                    MMA_F16(acc[mi][2*np],   ah[mi], bh4[0], bh4[1]);
                    MMA_F16(acc[mi][2*np],   al[mi], bh4[0], bh4[1]);
                    MMA_F16(acc[mi][2*np+1], ah[mi], bh4[2], bh4[3]);
                    MMA_F16(acc[mi][2*np+1], al[mi], bh4[2], bh4[3]);
                }
            }
        }
    }

    const int er = lane >> 2;
    const int ec = (lane & 3) * 2;
    #pragma unroll
    for (int mi = 0; mi < 4; mi++) {
        #pragma unroll
        for (int nn = 0; nn < 4; nn++) {
            float* cp0 = C + (size_t)(bm + wr*64 + mi*16 + er) * N
                           + bn + wc*32 + nn*8 + ec;
            *(float2*)cp0         = make_float2(acc[mi][nn][0], acc[mi][nn][1]);
            *(float2*)(cp0 + 8*N) = make_float2(acc[mi][nn][2], acc[mi][nn][3]);
        }
    }
}

// ---------------- Flash attention (bf16x3), BM=64, 4 warps -------------------
#define FST 272
#define Q_OFF  0
#define QL_OFF (64*FST)
#define KH_OFF (2*64*FST)
#define KL_OFF (3*64*FST)
#define VH_OFF (4*64*FST)
#define VL_OFF (5*64*FST)
#define FLASH_SMEM (6*64*FST)           // 104448

__global__ void __launch_bounds__(128) flash_mma(
    const __nv_bfloat16* __restrict__ qh, const __nv_bfloat16* __restrict__ ql,
    const __nv_bfloat16* __restrict__ kh, const __nv_bfloat16* __restrict__ kl,
    const __nv_bfloat16* __restrict__ vh, const __nv_bfloat16* __restrict__ vl,
    __half* __restrict__ Yh, __half* __restrict__ Yl)
{
    extern __shared__ __align__(16) char smf[];
    const uint32_t sb = s2u(smf);
    const int tid  = threadIdx.x;
    const int lane = tid & 31;
    const int wid  = tid >> 5;
    const int qb   = gridDim.x - 1 - blockIdx.x;
    const int h    = blockIdx.y;
    const int b    = blockIdx.z;
    const int q0   = qb * 64;
    const int hkv  = h >> 2;
    const int mrow = wid * 16;

    const __nv_bfloat16* qhp = qh + ((size_t)(b*NH  + h  ) * SS + q0) * HD;
    const __nv_bfloat16* qlp = ql + ((size_t)(b*NH  + h  ) * SS + q0) * HD;
    const __nv_bfloat16* khp = kh + ((size_t)(b*NKV + hkv) * SS) * HD;
    const __nv_bfloat16* klp = kl + ((size_t)(b*NKV + hkv) * SS) * HD;
    const __nv_bfloat16* vhp = vh + ((size_t)(b*NKV + hkv) * SS) * HD;
    const __nv_bfloat16* vlp = vl + ((size_t)(b*NKV + hkv) * SS) * HD;

    #pragma unroll
    for (int i = 0; i < 8; i++) {
        int lin = tid + i*128;
        int r   = lin >> 4;
        int ch  = lin & 15;
        cp16(sb + Q_OFF  + r*FST + ch*16, qhp + (size_t)r*HD + ch*8);
        cp16(sb + QL_OFF + r*FST + ch*16, qlp + (size_t)r*HD + ch*8);
    }
    asm volatile("cp.async.commit_group;" ::: "memory");

    const int l8 = lane & 7;
    const int rA = ((lane >> 3) & 1) * 8 + l8;
    const int cA = ((lane >> 4) & 1) * 16;
    const int rB = ((lane >> 4) & 1) * 8 + l8;
    const int cB = ((lane >> 3) & 1) * 16;
    const int lr = lane >> 2;
    const int l4 = lane & 3;

    float O[16][4];
    #pragma unroll
    for (int j = 0; j < 16; j++)
        #pragma unroll
        for (int r = 0; r < 4; r++) O[j][r] = 0.f;
    float m0v = -1e30f, m1v = -1e30f, l0v = 0.f, l1v = 0.f;

    const int nkb = qb + 1;
    for (int kb = 0; kb < nkb; ++kb) {
        const int k0 = kb * 64;
        if (kb) __syncthreads();
        #pragma unroll
        for (int i = 0; i < 8; i++) {
            int lin = tid + i*128;
            int r   = lin >> 4;
            int ch  = lin & 15;
            size_t g = (size_t)(k0 + r)*HD + ch*8;
            uint32_t so = r*FST + ch*16;
            cp16(sb + KH_OFF + so, khp + g);
            cp16(sb + KL_OFF + so, klp + g);
            cp16(sb + VH_OFF + so, vhp + g);
            cp16(sb + VL_OFF + so, vlp + g);
        }
        asm volatile("cp.async.commit_group;" ::: "memory");
        asm volatile("cp.async.wait_group 0;" ::: "memory");
        __syncthreads();

        float S[8][4];
        #pragma unroll
        for (int j = 0; j < 8; j++)
            #pragma unroll
            for (int r = 0; r < 4; r++) S[j][r] = 0.f;

        #pragma unroll
        for (int kc = 0; kc < 8; kc++) {
            uint32_t qa_h[4], qa_l[4];
            uint32_t qaddr = sb + Q_OFF + (uint32_t)(mrow + rA)*FST + kc*32 + cA;
            LDSM4(qa_h, qaddr);
            LDSM4(qa_l, qaddr + QL_OFF);
            #pragma unroll
            for (int ng = 0; ng < 4; ng++) {
                uint32_t kaddr = sb + KH_OFF + (uint32_t)(ng*16 + rB)*FST + kc*32 + cB;
                uint32_t bh4[4], bl4[4];
                LDSM4(bh4, kaddr);
                LDSM4(bl4, kaddr + (KL_OFF - KH_OFF));
                MMA_BF16(S[2*ng],   qa_h, bh4[0], bh4[1]);
                MMA_BF16(S[2*ng],   qa_h, bl4[0], bl4[1]);
                MMA_BF16(S[2*ng],   qa_l, bh4[0], bh4[1]);
                MMA_BF16(S[2*ng+1], qa_h, bh4[2], bh4[3]);
                MMA_BF16(S[2*ng+1], qa_h, bl4[2], bl4[3]);
                MMA_BF16(S[2*ng+1], qa_l, bh4[2], bh4[3]);
            }
        }

        if (kb == qb) {
            int row0 = q0 + mrow + lr;
            int row1 = row0 + 8;
            #pragma unroll
            for (int j = 0; j < 8; j++) {
                int c0 = k0 + 8*j + 2*l4;
                if (c0     > row0) S[j][0] = -1e30f;
                if (c0 + 1 > row0) S[j][1] = -1e30f;
                if (c0     > row1) S[j][2] = -1e30f;
                if (c0 + 1 > row1) S[j][3] = -1e30f;
            }
        }

        {
            float mx = -1e30f;
            #pragma unroll
            for (int j = 0; j < 8; j++) mx = fmaxf(mx, fmaxf(S[j][0], S[j][1]));
            mx = fmaxf(mx, __shfl_xor_sync(0xffffffffu, mx, 1));
            mx = fmaxf(mx, __shfl_xor_sync(0xffffffffu, mx, 2));
            float mn = fmaxf(m0v, mx);
            float corr = ex2f(m0v - mn);
            m0v = mn;
            float rs = 0.f;
            #pragma unroll
            for (int j = 0; j < 8; j++) {
                S[j][0] = ex2f(S[j][0] - mn);
                S[j][1] = ex2f(S[j][1] - mn);
                rs += S[j][0] + S[j][1];
            }
            rs += __shfl_xor_sync(0xffffffffu, rs, 1);
            rs += __shfl_xor_sync(0xffffffffu, rs, 2);
            l0v = l0v * corr + rs;
            #pragma unroll
            for (int j = 0; j < 16; j++) { O[j][0] *= corr; O[j][1] *= corr; }
        }
        {
            float mx = -1e30f;
            #pragma unroll
            for (int j = 0; j < 8; j++) mx = fmaxf(mx, fmaxf(S[j][2], S[j][3]));
            mx = fmaxf(mx, __shfl_xor_sync(0xffffffffu, mx, 1));
            mx = fmaxf(mx, __shfl_xor_sync(0xffffffffu, mx, 2));
            float mn = fmaxf(m1v, mx);
            float corr = ex2f(m1v - mn);
            m1v = mn;
            float rs = 0.f;
            #pragma unroll
            for (int j = 0; j < 8; j++) {
                S[j][2] = ex2f(S[j][2] - mn);
                S[j][3] = ex2f(S[j][3] - mn);
                rs += S[j][2] + S[j][3];
            }
            rs += __shfl_xor_sync(0xffffffffu, rs, 1);
            rs += __shfl_xor_sync(0xffffffffu, rs, 2);
            l1v = l1v * corr + rs;
            #pragma unroll
            for (int j = 0; j < 16; j++) { O[j][2] *= corr; O[j][3] *= corr; }
        }

        #pragma unroll
        for (int t = 0; t < 4; t++) {
            uint32_t Ahf[4], Alf[4];
            Ahf[0] = cvt2(S[2*t][1],   S[2*t][0]);
            Ahf[1] = cvt2(S[2*t][3],   S[2*t][2]);
            Ahf[2] = cvt2(S[2*t+1][1], S[2*t+1][0]);
            Ahf[3] = cvt2(S[2*t+1][3], S[2*t+1][2]);
            Alf[0] = cvt2(S[2*t][1]   - hi_f(Ahf[0]), S[2*t][0]   - lo_f(Ahf[0]));
            Alf[1] = cvt2(S[2*t][3]   - hi_f(Ahf[1]), S[2*t][2]   - lo_f(Ahf[1]));
            Alf[2] = cvt2(S[2*t+1][1] - hi_f(Ahf[2]), S[2*t+1][0] - lo_f(Ahf[2]));
            Alf[3] = cvt2(S[2*t+1][3] - hi_f(Ahf[3]), S[2*t+1][2] - lo_f(Ahf[3]));
            #pragma unroll
            for (int dg = 0; dg < 8; dg++) {
                uint32_t vaddr = sb + VH_OFF + (uint32_t)(t*16 + rA)*FST + dg*32 + cA;
                uint32_t vhf[4], vlf[4];
                LDSM4T(vhf, vaddr);
                LDSM4T(vlf, vaddr + (VL_OFF - VH_OFF));
                MMA_BF16(O[2*dg],   Ahf, vhf[0], vhf[1]);
                MMA_BF16(O[2*dg],   Ahf, vlf[0], vlf[1]);
                MMA_BF16(O[2*dg],   Alf, vhf[0], vhf[1]);
                MMA_BF16(O[2*dg+1], Ahf, vhf[2], vhf[3]);
                MMA_BF16(O[2*dg+1], Ahf, vlf[2], vlf[3]);
                MMA_BF16(O[2*dg+1], Alf, vhf[2], vhf[3]);
            }
        }
    }

    // ---- write O as fp16 hi + fp16 residual (feeds gemm_out2) ----
    float inv0 = 1.0f / l0v;
    float inv1 = 1.0f / l1v;
    int row0 = q0 + mrow + lr;
    size_t base0 = (size_t)(b*SS + row0) * DD + h*HD;
    size_t base1 = base0 + (size_t)8 * DD;
    #pragma unroll
    for (int j = 0; j < 16; j++) {
        float a0 = O[j][0]*inv0, a1 = O[j][1]*inv0;
        float b0 = O[j][2]*inv1, b1 = O[j][3]*inv1;
        uint32_t h0 = pack_h2(a0, a1);
        uint32_t l0 = pack_h2(a0 - h2lo(h0), a1 - h2hi(h0));
        uint32_t h1 = pack_h2(b0, b1);
        uint32_t l1 = pack_h2(b0 - h2lo(h1), b1 - h2hi(h1));
        *(uint32_t*)(Yh + base0 + 8*j + 2*l4) = h0;
        *(uint32_t*)(Yl + base0 + 8*j + 2*l4) = l0;
        *(uint32_t*)(Yh + base1 + 8*j + 2*l4) = h1;
        *(uint32_t*)(Yl + base1 + 8*j + 2*l4) = l1;
    }
}

// ---------------- launch ----------------------------------------------------
extern "C" void kernel_launch(void* const* d_in, const int* in_sizes, int n_in,
                              void* d_out, int out_size)
{
    const float* x     = (const float*)d_in[0];
    const float* freqs = (const float*)d_in[1];
    const float* wqkv  = (const float*)d_in[2];
    const float* wo    = (const float*)d_in[3];
    const float* qw    = (const float*)d_in[4];
    const float* kw    = (const float*)d_in[5];
    float* out = (float*)d_out;

    __half *p_xh, *p_wqh, *p_woh, *p_yh, *p_yl;
    __nv_bfloat16 *p_qh, *p_ql, *p_kh, *p_kl, *p_vh, *p_vl;
    cudaGetSymbolAddress((void**)&p_xh,  g_xh);
    cudaGetSymbolAddress((void**)&p_wqh, g_wqh);
    cudaGetSymbolAddress((void**)&p_woh, g_woh);
    cudaGetSymbolAddress((void**)&p_yh,  g_yh);
    cudaGetSymbolAddress((void**)&p_yl,  g_yl);
    cudaGetSymbolAddress((void**)&p_qh,  g_qh);
    cudaGetSymbolAddress((void**)&p_ql,  g_ql);
    cudaGetSymbolAddress((void**)&p_kh,  g_kh);
    cudaGetSymbolAddress((void**)&p_kl,  g_kl);
    cudaGetSymbolAddress((void**)&p_vh,  g_vh);
    cudaGetSymbolAddress((void**)&p_vl,  g_vl);

    cudaFuncSetAttribute(gemm_qkv,
                         cudaFuncAttributeMaxDynamicSharedMemorySize, HGSMEM);
    cudaFuncSetAttribute(gemm_out2,
                         cudaFuncAttributeMaxDynamicSharedMemorySize, OGSMEM);
    cudaFuncSetAttribute(flash_mma,
                         cudaFuncAttributeMaxDynamicSharedMemorySize, FLASH_SMEM);

    const int n4_x  = BB*SS*DD / 4;
    const int n4_wq = QKVE*DD  / 4;
    const int n4_wo = DD*DD    / 4;

    // 0) converts (all fp16 single now)
    to_half<<<n4_x /256, 256>>>((const float4*)x,    (uint2*)p_xh,  n4_x);
    to_half<<<n4_wq/256, 256>>>((const float4*)wqkv, (uint2*)p_wqh, n4_wq);
    to_half<<<n4_wo/256, 256>>>((const float4*)wo,   (uint2*)p_woh, n4_wo);

    // 1) fused QKV projection + RMSNorm + RoPE + bf16 split
    gemm_qkv<<<dim3(EHEADS, (BB*SS)/128), 256, HGSMEM>>>(
        p_xh, p_wqh, freqs, qw, kw,
        p_qh, p_ql, p_kh, p_kl, p_vh, p_vl);

    // 2) Flash attention (bf16x3); writes y as fp16 hi/lo (exact split)
    flash_mma<<<dim3(SS/64, NH, BB), 128, FLASH_SMEM>>>(
        p_qh, p_ql, p_kh, p_kl, p_vh, p_vl, p_yh, p_yl);

    // 3) Output projection (fp16 2-pass: y exact, wo quantized)
    gemm_out2<<<dim3(DD/128, (BB*SS)/128), 256, OGSMEM>>>(
        p_yh, p_yl, p_woh, out, DD, NH*HD);
}

// round 16
// speedup vs baseline: 1.2549x; 1.1040x over previous
#include <cuda_runtime.h>
#include <cuda_fp16.h>
#include <math.h>
#include <stdint.h>

// Problem constants
#define BB   2
#define SS   2048
#define DD   2048
#define NH   16
#define NKV  4
#define HD   128
#define EHEADS (NH + 2*NKV)          // 24
#define QKVE (EHEADS * HD)           // 3072

// ---------------- scratch (device globals; no allocation allowed) ----------
__device__ __align__(16) __half g_xh [(size_t)BB*SS*DD];
__device__ __align__(16) __half g_wqh[(size_t)QKVE*DD];
__device__ __align__(16) __half g_woh[(size_t)DD*DD];          // wo fp16 (single)
__device__ __align__(16) __half g_yh [(size_t)BB*SS*DD];       // y fp16 hi
__device__ __align__(16) __half g_yl [(size_t)BB*SS*DD];       // y fp16 lo (residual)
__device__ __align__(16) __half g_qh [(size_t)BB*NH *SS*HD];   // q fp16 hi
__device__ __align__(16) __half g_ql [(size_t)BB*NH *SS*HD];   // q fp16 lo (residual)
__device__ __align__(16) __half g_kh [(size_t)BB*NKV*SS*HD];   // k fp16 (single)
__device__ __align__(16) __half g_vh [(size_t)BB*NKV*SS*HD];   // v fp16 (single)

// ---------------- helpers ----------------------------------------------------
__device__ __forceinline__ float ex2f(float x) {
    float y;
    asm("ex2.approx.ftz.f32 %0, %1;" : "=f"(y) : "f"(x));
    return y;
}
__device__ __forceinline__ uint32_t s2u(const void* p) {
    uint32_t r;
    asm("{ .reg .u64 t; cvta.to.shared.u64 t, %1; cvt.u32.u64 %0, t; }" : "=r"(r) : "l"(p));
    return r;
}
__device__ __forceinline__ void cp16(uint32_t dst, const void* src) {
    asm volatile("cp.async.cg.shared.global [%0], [%1], 16;" :: "r"(dst), "l"(src));
}
__device__ __forceinline__ uint32_t pack_h2(float lo, float hi) {
    __half2 h = __floats2half2_rn(lo, hi);
    return *reinterpret_cast<uint32_t*>(&h);
}
__device__ __forceinline__ float h2lo(uint32_t u) {
    __half2 h = *reinterpret_cast<__half2*>(&u);
    return __low2float(h);
}
__device__ __forceinline__ float h2hi(uint32_t u) {
    __half2 h = *reinterpret_cast<__half2*>(&u);
    return __high2float(h);
}

#define LDSM4(r, addr) \
    asm volatile("ldmatrix.sync.aligned.m8n8.x4.shared.b16 {%0,%1,%2,%3}, [%4];" \
        : "=r"((r)[0]), "=r"((r)[1]), "=r"((r)[2]), "=r"((r)[3]) : "r"(addr))
#define LDSM4T(r, addr) \
    asm volatile("ldmatrix.sync.aligned.m8n8.x4.trans.shared.b16 {%0,%1,%2,%3}, [%4];" \
        : "=r"((r)[0]), "=r"((r)[1]), "=r"((r)[2]), "=r"((r)[3]) : "r"(addr))

#define MMA_F16(d, a, b0v, b1v) \
    asm volatile("mma.sync.aligned.m16n8k16.row.col.f32.f16.f16.f32 " \
        "{%0,%1,%2,%3}, {%4,%5,%6,%7}, {%8,%9}, {%0,%1,%2,%3};" \
        : "+f"((d)[0]), "+f"((d)[1]), "+f"((d)[2]), "+f"((d)[3]) \
        : "r"((a)[0]), "r"((a)[1]), "r"((a)[2]), "r"((a)[3]), "r"(b0v), "r"(b1v))

// ---------------- converters --------------------------------------------------
__global__ void __launch_bounds__(256) to_half(const float4* __restrict__ src,
                                               uint2* __restrict__ dst, int n4)
{
    int i = blockIdx.x * 256 + threadIdx.x;
    if (i >= n4) return;
    float4 v = src[i];
    dst[i] = make_uint2(pack_h2(v.x, v.y), pack_h2(v.z, v.w));
}

// ---------------- fused QKV GEMM + RMSNorm + RoPE + fp16 emit ----------------
// q -> exact fp16 hi/lo split; k, v -> single fp16.
#define QSCALE 0.12751943f   // (1/sqrt(128)) * log2(e)
#define HSTG   10240
#define HSTAGE (2*HSTG)
#define HGSMEM (3*HSTAGE)            // 61440

__global__ void __launch_bounds__(256) gemm_qkv(
    const __half* __restrict__ Ah, const __half* __restrict__ Bh,
    const float* __restrict__ freqs,
    const float* __restrict__ qw, const float* __restrict__ kw,
    __half* __restrict__ qh, __half* __restrict__ ql,
    __half* __restrict__ kh, __half* __restrict__ vh)
{
    const int K = DD;
    extern __shared__ __align__(16) char smg[];
    const uint32_t sb = s2u(smg);
    const int tid  = threadIdx.x;
    const int lane = tid & 31;
    const int wid  = tid >> 5;
    const int wr   = wid >> 2;
    const int wc   = wid & 3;
    const int h    = blockIdx.x;
    const int bm   = blockIdx.y << 7;
    const int bn   = h << 7;
    const int nk   = K >> 5;

    float acc[4][4][4];
    #pragma unroll
    for (int i = 0; i < 4; i++)
        #pragma unroll
        for (int j = 0; j < 4; j++)
            #pragma unroll
            for (int r = 0; r < 4; r++) acc[i][j][r] = 0.f;

    const int l8     = lane & 7;
    const int rowA   = ((lane >> 3) & 1) * 8 + l8;
    const int kbyteA = ((lane >> 4) & 1) * 16;
    const int rowB   = ((lane >> 4) & 1) * 8 + l8;
    const int byteB  = ((lane >> 3) & 1) * 16;

    auto fill = [&](int s, int kc) {
        const int k0 = kc << 5;
        const uint32_t dst = sb + s * HSTAGE;
        #pragma unroll
        for (int i = 0; i < 2; i++) {
            int lin = tid + i * 256;
            int row = lin >> 2;
            int ch  = lin & 3;
            uint32_t so = row * 80 + ch * 16;
            cp16(dst +        so, Ah + (size_t)(bm + row) * K + k0 + ch * 8);
            cp16(dst + HSTG + so, Bh + (size_t)(bn + row) * K + k0 + ch * 8);
        }
        asm volatile("cp.async.commit_group;" ::: "memory");
    };

    fill(0, 0);
    fill(1, 1);

    for (int t = 0; t < nk; ++t) {
        if (t + 1 < nk) asm volatile("cp.async.wait_group 1;" ::: "memory");
        else            asm volatile("cp.async.wait_group 0;" ::: "memory");
        __syncthreads();

        if (t + 2 < nk) fill((t + 2) % 3, t + 2);

        const uint32_t st = sb + (t % 3) * HSTAGE;
        #pragma unroll
        for (int kh2 = 0; kh2 < 2; kh2++) {
            uint32_t ah[4][4];
            #pragma unroll
            for (int mi = 0; mi < 4; mi++) {
                uint32_t aaddr = st + (uint32_t)(wr*64 + mi*16 + rowA) * 80
                               + kh2*32 + kbyteA;
                LDSM4(ah[mi], aaddr);
            }
            #pragma unroll
            for (int np = 0; np < 2; np++) {
                uint32_t baddr = st + HSTG + (uint32_t)(wc*32 + np*16 + rowB) * 80
                               + kh2*32 + byteB;
                uint32_t bh4[4];
                LDSM4(bh4, baddr);
                #pragma unroll
                for (int mi = 0; mi < 4; mi++) {
                    MMA_F16(acc[mi][2*np],   ah[mi], bh4[0], bh4[1]);
                    MMA_F16(acc[mi][2*np+1], ah[mi], bh4[2], bh4[3]);
                }
            }
        }
    }

    // ---- fused epilogue: rmsnorm + rope + fp16 emit ----
    __syncthreads();
    float* red = (float*)smg;
    const int er = lane >> 2;
    const int ec = (lane & 3) * 2;
    const bool isq = (h < NH);
    const bool isv = (h >= NH + NKV);

    #pragma unroll
    for (int mi = 0; mi < 4; mi++) {
        float s0 = 0.f, s1 = 0.f;
        #pragma unroll
        for (int nn = 0; nn < 4; nn++) {
            s0 += acc[mi][nn][0]*acc[mi][nn][0] + acc[mi][nn][1]*acc[mi][nn][1];
            s1 += acc[mi][nn][2]*acc[mi][nn][2] + acc[mi][nn][3]*acc[mi][nn][3];
        }
        s0 += __shfl_xor_sync(0xffffffffu, s0, 1);
        s0 += __shfl_xor_sync(0xffffffffu, s0, 2);
        s1 += __shfl_xor_sync(0xffffffffu, s1, 1);
        s1 += __shfl_xor_sync(0xffffffffu, s1, 2);
        if ((lane & 3) == 0) {
            red[(wr*64 + mi*16 + er)     * 4 + wc] = s0;
            red[(wr*64 + mi*16 + er + 8) * 4 + wc] = s1;
        }
    }
    __syncthreads();

    const float* wn = isq ? qw : kw;
    const float fold = isq ? QSCALE : 1.0f;

    #pragma unroll
    for (int mi = 0; mi < 4; mi++) {
        #pragma unroll
        for (int half = 0; half < 2; half++) {
            const int row = wr*64 + mi*16 + er + half*8;
            const int n   = bm + row;
            const int b   = n >> 11;
            const int s   = n & 2047;
            float inv = 1.0f;
            if (!isv) {
                float ssq = red[row*4+0] + red[row*4+1] + red[row*4+2] + red[row*4+3];
                inv = rsqrtf(ssq * (1.0f / HD) + 1e-6f) * fold;
            }
            size_t drow;
            if (isq)      drow = (size_t)(b*NH  + h)           * SS + s;
            else if (!isv)drow = (size_t)(b*NKV + h - NH)      * SS + s;
            else          drow = (size_t)(b*NKV + h - NH - NKV)* SS + s;

            #pragma unroll
            for (int nn = 0; nn < 4; nn++) {
                const int col = wc*32 + nn*8 + ec;
                float v0 = acc[mi][nn][half*2];
                float v1 = acc[mi][nn][half*2+1];
                float o0, o1;
                if (!isv) {
                    float2 wv = *(const float2*)(wn + col);
                    float2 f  = *(const float2*)(freqs + (size_t)s*128 + col);
                    float x0 = v0 * inv * wv.x;
                    float x1 = v1 * inv * wv.y;
                    o0 = x0*f.x - x1*f.y;
                    o1 = x1*f.x + x0*f.y;
                } else {
                    o0 = v0; o1 = v1;
                }
                uint32_t hp = pack_h2(o0, o1);
                if (isq) {
                    uint32_t lp = pack_h2(o0 - h2lo(hp), o1 - h2hi(hp));
                    *(uint32_t*)(qh + drow*HD + col) = hp;
                    *(uint32_t*)(ql + drow*HD + col) = lp;
                } else if (!isv) {
                    *(uint32_t*)(kh + drow*HD + col) = hp;
                } else {
                    *(uint32_t*)(vh + drow*HD + col) = hp;
                }
            }
        }
    }
}

// ---------------- out-projection GEMM: fp16 2-pass (y exact-split, wo fp16) --
#define OSTG   10240
#define OSTAGE (3*OSTG)              // Ah, Al, Bh
#define OGSMEM (3*OSTAGE)            // 92160

__global__ void __launch_bounds__(256) gemm_out2(
    const __half* __restrict__ Ah, const __half* __restrict__ Al,
    const __half* __restrict__ Bh,
    float* __restrict__ C, int N, int K)
{
    extern __shared__ __align__(16) char smg[];
    const uint32_t sb = s2u(smg);
    const int tid  = threadIdx.x;
    const int lane = tid & 31;
    const int wid  = tid >> 5;
    const int wr   = wid >> 2;
    const int wc   = wid & 3;
    const int bm   = blockIdx.y << 7;
    const int bn   = blockIdx.x << 7;
    const int nk   = K >> 5;

    float acc[4][4][4];
    #pragma unroll
    for (int i = 0; i < 4; i++)
        #pragma unroll
        for (int j = 0; j < 4; j++)
            #pragma unroll
            for (int r = 0; r < 4; r++) acc[i][j][r] = 0.f;

    const int l8     = lane & 7;
    const int rowA   = ((lane >> 3) & 1) * 8 + l8;
    const int kbyteA = ((lane >> 4) & 1) * 16;
    const int rowB   = ((lane >> 4) & 1) * 8 + l8;
    const int byteB  = ((lane >> 3) & 1) * 16;

    auto fill = [&](int s, int kc) {
        const int k0 = kc << 5;
        const uint32_t dst = sb + s * OSTAGE;
        #pragma unroll
        for (int i = 0; i < 2; i++) {
            int lin = tid + i * 256;
            int row = lin >> 2;
            int ch  = lin & 3;
            uint32_t so = row * 80 + ch * 16;
            size_t ga = (size_t)(bm + row) * K + k0 + ch * 8;
            cp16(dst +          so, Ah + ga);
            cp16(dst + OSTG   + so, Al + ga);
            cp16(dst + 2*OSTG + so, Bh + (size_t)(bn + row) * K + k0 + ch * 8);
        }
        asm volatile("cp.async.commit_group;" ::: "memory");
    };

    fill(0, 0);
    if (nk > 1) fill(1, 1);

    for (int t = 0; t < nk; ++t) {
        if (t + 1 < nk) asm volatile("cp.async.wait_group 1;" ::: "memory");
        else            asm volatile("cp.async.wait_group 0;" ::: "memory");
        __syncthreads();

        if (t + 2 < nk) fill((t + 2) % 3, t + 2);

        const uint32_t st = sb + (t % 3) * OSTAGE;
        #pragma unroll
        for (int kh = 0; kh < 2; kh++) {
            uint32_t ah[4][4], al[4][4];
            #pragma unroll
            for (int mi = 0; mi < 4; mi++) {
                uint32_t aaddr = st + (uint32_t)(wr*64 + mi*16 + rowA) * 80
                               + kh*32 + kbyteA;
                LDSM4(ah[mi], aaddr);
                LDSM4(al[mi], aaddr + OSTG);
            }
            #pragma unroll
            for (int np = 0; np < 2; np++) {
                uint32_t baddr = st + 2*OSTG + (uint32_t)(wc*32 + np*16 + rowB) * 80
                               + kh*32 + byteB;
                uint32_t bh4[4];
                LDSM4(bh4, baddr);
                #pragma unroll
                for (int mi = 0; mi < 4; mi++) {
                    MMA_F16(acc[mi][2*np],   ah[mi], bh4[0], bh4[1]);
                    MMA_F16(acc[mi][2*np],   al[mi], bh4[0], bh4[1]);
                    MMA_F16(acc[mi][2*np+1], ah[mi], bh4[2], bh4[3]);
                    MMA_F16(acc[mi][2*np+1], al[mi], bh4[2], bh4[3]);
                }
            }
        }
    }

    const int er = lane >> 2;
    const int ec = (lane & 3) * 2;
    #pragma unroll
    for (int mi = 0; mi < 4; mi++) {
        #pragma unroll
        for (int nn = 0; nn < 4; nn++) {
            float* cp0 = C + (size_t)(bm + wr*64 + mi*16 + er) * N
                           + bn + wc*32 + nn*8 + ec;
            *(float2*)cp0         = make_float2(acc[mi][nn][0], acc[mi][nn][1]);
            *(float2*)(cp0 + 8*N) = make_float2(acc[mi][nn][2], acc[mi][nn][3]);
        }
    }
}

// ---------------- Flash attention (fp16 2-pass), BM=64, 4 warps --------------
// Q exact hi/lo split; K, V single fp16. P exact hi/lo split in registers.
#define FST 272
#define Q_OFF  0
#define QL_OFF (64*FST)
#define K_OFF  (2*64*FST)
#define V_OFF  (3*64*FST)
#define FLASH_SMEM (4*64*FST)           // 69632

__global__ void __launch_bounds__(128) flash_mma(
    const __half* __restrict__ qh, const __half* __restrict__ ql,
    const __half* __restrict__ kh, const __half* __restrict__ vh,
    __half* __restrict__ Yh, __half* __restrict__ Yl)
{
    extern __shared__ __align__(16) char smf[];
    const uint32_t sb = s2u(smf);
    const int tid  = threadIdx.x;
    const int lane = tid & 31;
    const int wid  = tid >> 5;
    const int qb   = gridDim.x - 1 - blockIdx.x;
    const int h    = blockIdx.y;
    const int b    = blockIdx.z;
    const int q0   = qb * 64;
    const int hkv  = h >> 2;
    const int mrow = wid * 16;

    const __half* qhp = qh + ((size_t)(b*NH  + h  ) * SS + q0) * HD;
    const __half* qlp = ql + ((size_t)(b*NH  + h  ) * SS + q0) * HD;
    const __half* khp = kh + ((size_t)(b*NKV + hkv) * SS) * HD;
    const __half* vhp = vh + ((size_t)(b*NKV + hkv) * SS) * HD;

    #pragma unroll
    for (int i = 0; i < 8; i++) {
        int lin = tid + i*128;
        int r   = lin >> 4;
        int ch  = lin & 15;
        cp16(sb + Q_OFF  + r*FST + ch*16, qhp + (size_t)r*HD + ch*8);
        cp16(sb + QL_OFF + r*FST + ch*16, qlp + (size_t)r*HD + ch*8);
    }
    asm volatile("cp.async.commit_group;" ::: "memory");

    const int l8 = lane & 7;
    const int rA = ((lane >> 3) & 1) * 8 + l8;
    const int cA = ((lane >> 4) & 1) * 16;
    const int rB = ((lane >> 4) & 1) * 8 + l8;
    const int cB = ((lane >> 3) & 1) * 16;
    const int lr = lane >> 2;
    const int l4 = lane & 3;

    float O[16][4];
    #pragma unroll
    for (int j = 0; j < 16; j++)
        #pragma unroll
        for (int r = 0; r < 4; r++) O[j][r] = 0.f;
    float m0v = -1e30f, m1v = -1e30f, l0v = 0.f, l1v = 0.f;

    const int nkb = qb + 1;
    for (int kb = 0; kb < nkb; ++kb) {
        const int k0 = kb * 64;
        if (kb) __syncthreads();
        #pragma unroll
        for (int i = 0; i < 8; i++) {
            int lin = tid + i*128;
            int r   = lin >> 4;
            int ch  = lin & 15;
            size_t g = (size_t)(k0 + r)*HD + ch*8;
            uint32_t so = r*FST + ch*16;
            cp16(sb + K_OFF + so, khp + g);
            cp16(sb + V_OFF + so, vhp + g);
        }
        asm volatile("cp.async.commit_group;" ::: "memory");
        asm volatile("cp.async.wait_group 0;" ::: "memory");
        __syncthreads();

        float S[8][4];
        #pragma unroll
        for (int j = 0; j < 8; j++)
            #pragma unroll
            for (int r = 0; r < 4; r++) S[j][r] = 0.f;

        #pragma unroll
        for (int kc = 0; kc < 8; kc++) {
            uint32_t qa_h[4], qa_l[4];
            uint32_t qaddr = sb + Q_OFF + (uint32_t)(mrow + rA)*FST + kc*32 + cA;
            LDSM4(qa_h, qaddr);
            LDSM4(qa_l, qaddr + QL_OFF);
            #pragma unroll
            for (int ng = 0; ng < 4; ng++) {
                uint32_t kaddr = sb + K_OFF + (uint32_t)(ng*16 + rB)*FST + kc*32 + cB;
                uint32_t bh4[4];
                LDSM4(bh4, kaddr);
                MMA_F16(S[2*ng],   qa_h, bh4[0], bh4[1]);
                MMA_F16(S[2*ng],   qa_l, bh4[0], bh4[1]);
                MMA_F16(S[2*ng+1], qa_h, bh4[2], bh4[3]);
                MMA_F16(S[2*ng+1], qa_l, bh4[2], bh4[3]);
            }
        }

        if (kb == qb) {
            int row0 = q0 + mrow + lr;
            int row1 = row0 + 8;
            #pragma unroll
            for (int j = 0; j < 8; j++) {
                int c0 = k0 + 8*j + 2*l4;
                if (c0     > row0) S[j][0] = -1e30f;
                if (c0 + 1 > row0) S[j][1] = -1e30f;
                if (c0     > row1) S[j][2] = -1e30f;
                if (c0 + 1 > row1) S[j][3] = -1e30f;
            }
        }

        {
            float mx = -1e30f;
            #pragma unroll
            for (int j = 0; j < 8; j++) mx = fmaxf(mx, fmaxf(S[j][0], S[j][1]));
            mx = fmaxf(mx, __shfl_xor_sync(0xffffffffu, mx, 1));
            mx = fmaxf(mx, __shfl_xor_sync(0xffffffffu, mx, 2));
            float mn = fmaxf(m0v, mx);
            float corr = ex2f(m0v - mn);
            m0v = mn;
            float rs = 0.f;
            #pragma unroll
            for (int j = 0; j < 8; j++) {
                S[j][0] = ex2f(S[j][0] - mn);
                S[j][1] = ex2f(S[j][1] - mn);
                rs += S[j][0] + S[j][1];
            }
            rs += __shfl_xor_sync(0xffffffffu, rs, 1);
            rs += __shfl_xor_sync(0xffffffffu, rs, 2);
            l0v = l0v * corr + rs;
            #pragma unroll
            for (int j = 0; j < 16; j++) { O[j][0] *= corr; O[j][1] *= corr; }
        }
        {
            float mx = -1e30f;
            #pragma unroll
            for (int j = 0; j < 8; j++) mx = fmaxf(mx, fmaxf(S[j][2], S[j][3]));
            mx = fmaxf(mx, __shfl_xor_sync(0xffffffffu, mx, 1));
            mx = fmaxf(mx, __shfl_xor_sync(0xffffffffu, mx, 2));
            float mn = fmaxf(m1v, mx);
            float corr = ex2f(m1v - mn);
            m1v = mn;
            float rs = 0.f;
            #pragma unroll
            for (int j = 0; j < 8; j++) {
                S[j][2] = ex2f(S[j][2] - mn);
                S[j][3] = ex2f(S[j][3] - mn);
                rs += S[j][2] + S[j][3];
            }
            rs += __shfl_xor_sync(0xffffffffu, rs, 1);
            rs += __shfl_xor_sync(0xffffffffu, rs, 2);
            l1v = l1v * corr + rs;
            #pragma unroll
            for (int j = 0; j < 16; j++) { O[j][2] *= corr; O[j][3] *= corr; }
        }

        // ---- O += P V (P exact fp16 hi/lo split; V single fp16) ----
        #pragma unroll
        for (int t = 0; t < 4; t++) {
            uint32_t Ahf[4], Alf[4];
            Ahf[0] = pack_h2(S[2*t][0],   S[2*t][1]);
            Ahf[1] = pack_h2(S[2*t][2],   S[2*t][3]);
            Ahf[2] = pack_h2(S[2*t+1][0], S[2*t+1][1]);
            Ahf[3] = pack_h2(S[2*t+1][2], S[2*t+1][3]);
            Alf[0] = pack_h2(S[2*t][0]   - h2lo(Ahf[0]), S[2*t][1]   - h2hi(Ahf[0]));
            Alf[1] = pack_h2(S[2*t][2]   - h2lo(Ahf[1]), S[2*t][3]   - h2hi(Ahf[1]));
            Alf[2] = pack_h2(S[2*t+1][0] - h2lo(Ahf[2]), S[2*t+1][1] - h2hi(Ahf[2]));
            Alf[3] = pack_h2(S[2*t+1][2] - h2lo(Ahf[3]), S[2*t+1][3] - h2hi(Ahf[3]));
            #pragma unroll
            for (int dg = 0; dg < 8; dg++) {
                uint32_t vaddr = sb + V_OFF + (uint32_t)(t*16 + rA)*FST + dg*32 + cA;
                uint32_t vf[4];
                LDSM4T(vf, vaddr);
                MMA_F16(O[2*dg],   Ahf, vf[0], vf[1]);
                MMA_F16(O[2*dg],   Alf, vf[0], vf[1]);
                MMA_F16(O[2*dg+1], Ahf, vf[2], vf[3]);
                MMA_F16(O[2*dg+1], Alf, vf[2], vf[3]);
            }
        }
    }

    // ---- write O as fp16 hi + fp16 residual (feeds gemm_out2) ----
    float inv0 = 1.0f / l0v;
    float inv1 = 1.0f / l1v;
    int row0 = q0 + mrow + lr;
    size_t base0 = (size_t)(b*SS + row0) * DD + h*HD;
    size_t base1 = base0 + (size_t)8 * DD;
    #pragma unroll
    for (int j = 0; j < 16; j++) {
        float a0 = O[j][0]*inv0, a1 = O[j][1]*inv0;
        float b0 = O[j][2]*inv1, b1 = O[j][3]*inv1;
        uint32_t h0 = pack_h2(a0, a1);
        uint32_t l0 = pack_h2(a0 - h2lo(h0), a1 - h2hi(h0));
        uint32_t h1 = pack_h2(b0, b1);
        uint32_t l1 = pack_h2(b0 - h2lo(h1), b1 - h2hi(h1));
        *(uint32_t*)(Yh + base0 + 8*j + 2*l4) = h0;
        *(uint32_t*)(Yl + base0 + 8*j + 2*l4) = l0;
        *(uint32_t*)(Yh + base1 + 8*j + 2*l4) = h1;
        *(uint32_t*)(Yl + base1 + 8*j + 2*l4) = l1;
    }
}

// ---------------- launch ----------------------------------------------------
extern "C" void kernel_launch(void* const* d_in, const int* in_sizes, int n_in,
                              void* d_out, int out_size)
{
    const float* x     = (const float*)d_in[0];
    const float* freqs = (const float*)d_in[1];
    const float* wqkv  = (const float*)d_in[2];
    const float* wo    = (const float*)d_in[3];
    const float* qw    = (const float*)d_in[4];
    const float* kw    = (const float*)d_in[5];
    float* out = (float*)d_out;

    __half *p_xh, *p_wqh, *p_woh, *p_yh, *p_yl;
    __half *p_qh, *p_ql, *p_kh, *p_vh;
    cudaGetSymbolAddress((void**)&p_xh,  g_xh);
    cudaGetSymbolAddress((void**)&p_wqh, g_wqh);
    cudaGetSymbolAddress((void**)&p_woh, g_woh);
    cudaGetSymbolAddress((void**)&p_yh,  g_yh);
    cudaGetSymbolAddress((void**)&p_yl,  g_yl);
    cudaGetSymbolAddress((void**)&p_qh,  g_qh);
    cudaGetSymbolAddress((void**)&p_ql,  g_ql);
    cudaGetSymbolAddress((void**)&p_kh,  g_kh);
    cudaGetSymbolAddress((void**)&p_vh,  g_vh);

    cudaFuncSetAttribute(gemm_qkv,
                         cudaFuncAttributeMaxDynamicSharedMemorySize, HGSMEM);
    cudaFuncSetAttribute(gemm_out2,
                         cudaFuncAttributeMaxDynamicSharedMemorySize, OGSMEM);
    cudaFuncSetAttribute(flash_mma,
                         cudaFuncAttributeMaxDynamicSharedMemorySize, FLASH_SMEM);

    const int n4_x  = BB*SS*DD / 4;
    const int n4_wq = QKVE*DD  / 4;
    const int n4_wo = DD*DD    / 4;

    // 0) converts (all fp16 single)
    to_half<<<n4_x /256, 256>>>((const float4*)x,    (uint2*)p_xh,  n4_x);
    to_half<<<n4_wq/256, 256>>>((const float4*)wqkv, (uint2*)p_wqh, n4_wq);
    to_half<<<n4_wo/256, 256>>>((const float4*)wo,   (uint2*)p_woh, n4_wo);

    // 1) fused QKV projection + RMSNorm + RoPE (q exact fp16 split; k,v fp16)
    gemm_qkv<<<dim3(EHEADS, (BB*SS)/128), 256, HGSMEM>>>(
        p_xh, p_wqh, freqs, qw, kw,
        p_qh, p_ql, p_kh, p_vh);

    // 2) Flash attention (fp16 2-pass); writes y as fp16 hi/lo (exact split)
    flash_mma<<<dim3(SS/64, NH, BB), 128, FLASH_SMEM>>>(
        p_qh, p_ql, p_kh, p_vh, p_yh, p_yl);

    // 3) Output projection (fp16 2-pass: y exact, wo quantized)
    gemm_out2<<<dim3(DD/128, (BB*SS)/128), 256, OGSMEM>>>(
        p_yh, p_yl, p_woh, out, DD, NH*HD);
}

// round 17
// speedup vs baseline: 1.3348x; 1.0637x over previous
#include <cuda_runtime.h>
#include <cuda_fp16.h>
#include <math.h>
#include <stdint.h>

// Problem constants
#define BB   2
#define SS   2048
#define DD   2048
#define NH   16
#define NKV  4
#define HD   128
#define EHEADS (NH + 2*NKV)          // 24
#define QKVE (EHEADS * HD)           // 3072

// ---------------- scratch (device globals; no allocation allowed) ----------
__device__ __align__(16) __half g_xh [(size_t)BB*SS*DD];
__device__ __align__(16) __half g_wqh[(size_t)QKVE*DD];
__device__ __align__(16) __half g_woh[(size_t)DD*DD];          // wo fp16 (single)
__device__ __align__(16) __half g_yh [(size_t)BB*SS*DD];       // y fp16 hi
__device__ __align__(16) __half g_yl [(size_t)BB*SS*DD];       // y fp16 lo (residual)
__device__ __align__(16) __half g_qh [(size_t)BB*NH *SS*HD];   // q fp16 hi
__device__ __align__(16) __half g_ql [(size_t)BB*NH *SS*HD];   // q fp16 lo (residual)
__device__ __align__(16) __half g_kh [(size_t)BB*NKV*SS*HD];   // k fp16 (single, read)
__device__ __align__(16) __half g_kl [(size_t)BB*NKV*SS*HD];   // k lo (written, unread)
__device__ __align__(16) __half g_vh [(size_t)BB*NKV*SS*HD];   // v fp16 (single, read)
__device__ __align__(16) __half g_vl [(size_t)BB*NKV*SS*HD];   // v lo (written, unread)

// ---------------- helpers ----------------------------------------------------
__device__ __forceinline__ float ex2f(float x) {
    float y;
    asm("ex2.approx.ftz.f32 %0, %1;" : "=f"(y) : "f"(x));
    return y;
}
__device__ __forceinline__ uint32_t s2u(const void* p) {
    uint32_t r;
    asm("{ .reg .u64 t; cvta.to.shared.u64 t, %1; cvt.u32.u64 %0, t; }" : "=r"(r) : "l"(p));
    return r;
}
__device__ __forceinline__ void cp16(uint32_t dst, const void* src) {
    asm volatile("cp.async.cg.shared.global [%0], [%1], 16;" :: "r"(dst), "l"(src));
}
__device__ __forceinline__ uint32_t pack_h2(float lo, float hi) {
    __half2 h = __floats2half2_rn(lo, hi);
    return *reinterpret_cast<uint32_t*>(&h);
}
__device__ __forceinline__ float h2lo(uint32_t u) {
    __half2 h = *reinterpret_cast<__half2*>(&u);
    return __low2float(h);
}
__device__ __forceinline__ float h2hi(uint32_t u) {
    __half2 h = *reinterpret_cast<__half2*>(&u);
    return __high2float(h);
}

#define LDSM4(r, addr) \
    asm volatile("ldmatrix.sync.aligned.m8n8.x4.shared.b16 {%0,%1,%2,%3}, [%4];" \
        : "=r"((r)[0]), "=r"((r)[1]), "=r"((r)[2]), "=r"((r)[3]) : "r"(addr))
#define LDSM4T(r, addr) \
    asm volatile("ldmatrix.sync.aligned.m8n8.x4.trans.shared.b16 {%0,%1,%2,%3}, [%4];" \
        : "=r"((r)[0]), "=r"((r)[1]), "=r"((r)[2]), "=r"((r)[3]) : "r"(addr))

#define MMA_F16(d, a, b0v, b1v) \
    asm volatile("mma.sync.aligned.m16n8k16.row.col.f32.f16.f16.f32 " \
        "{%0,%1,%2,%3}, {%4,%5,%6,%7}, {%8,%9}, {%0,%1,%2,%3};" \
        : "+f"((d)[0]), "+f"((d)[1]), "+f"((d)[2]), "+f"((d)[3]) \
        : "r"((a)[0]), "r"((a)[1]), "r"((a)[2]), "r"((a)[3]), "r"(b0v), "r"(b1v))

// ---------------- converters --------------------------------------------------
__global__ void __launch_bounds__(256) to_half(const float4* __restrict__ src,
                                               uint2* __restrict__ dst, int n4)
{
    int i = blockIdx.x * 256 + threadIdx.x;
    if (i >= n4) return;
    float4 v = src[i];
    dst[i] = make_uint2(pack_h2(v.x, v.y), pack_h2(v.z, v.w));
}

// ---------------- fused QKV GEMM + RMSNorm + RoPE + fp16 emit ----------------
// All heads: compute hi+lo, store both through selected pointers (round-15
// epilogue shape -> restores ptxas mainloop scheduling). k/v lo arrays unread.
#define QSCALE 0.12751943f   // (1/sqrt(128)) * log2(e)
#define HSTG   10240
#define HSTAGE (2*HSTG)
#define HGSMEM (3*HSTAGE)            // 61440

__global__ void __launch_bounds__(256) gemm_qkv(
    const __half* __restrict__ Ah, const __half* __restrict__ Bh,
    const float* __restrict__ freqs,
    const float* __restrict__ qw, const float* __restrict__ kw,
    __half* __restrict__ qh, __half* __restrict__ ql,
    __half* __restrict__ kh, __half* __restrict__ kl,
    __half* __restrict__ vh, __half* __restrict__ vl)
{
    const int K = DD;
    extern __shared__ __align__(16) char smg[];
    const uint32_t sb = s2u(smg);
    const int tid  = threadIdx.x;
    const int lane = tid & 31;
    const int wid  = tid >> 5;
    const int wr   = wid >> 2;
    const int wc   = wid & 3;
    const int h    = blockIdx.x;
    const int bm   = blockIdx.y << 7;
    const int bn   = h << 7;
    const int nk   = K >> 5;

    float acc[4][4][4];
    #pragma unroll
    for (int i = 0; i < 4; i++)
        #pragma unroll
        for (int j = 0; j < 4; j++)
            #pragma unroll
            for (int r = 0; r < 4; r++) acc[i][j][r] = 0.f;

    const int l8     = lane & 7;
    const int rowA   = ((lane >> 3) & 1) * 8 + l8;
    const int kbyteA = ((lane >> 4) & 1) * 16;
    const int rowB   = ((lane >> 4) & 1) * 8 + l8;
    const int byteB  = ((lane >> 3) & 1) * 16;

    auto fill = [&](int s, int kc) {
        const int k0 = kc << 5;
        const uint32_t dst = sb + s * HSTAGE;
        #pragma unroll
        for (int i = 0; i < 2; i++) {
            int lin = tid + i * 256;
            int row = lin >> 2;
            int ch  = lin & 3;
            uint32_t so = row * 80 + ch * 16;
            cp16(dst +        so, Ah + (size_t)(bm + row) * K + k0 + ch * 8);
            cp16(dst + HSTG + so, Bh + (size_t)(bn + row) * K + k0 + ch * 8);
        }
        asm volatile("cp.async.commit_group;" ::: "memory");
    };

    fill(0, 0);
    fill(1, 1);

    for (int t = 0; t < nk; ++t) {
        if (t + 1 < nk) asm volatile("cp.async.wait_group 1;" ::: "memory");
        else            asm volatile("cp.async.wait_group 0;" ::: "memory");
        __syncthreads();

        if (t + 2 < nk) fill((t + 2) % 3, t + 2);

        const uint32_t st = sb + (t % 3) * HSTAGE;
        #pragma unroll
        for (int kh2 = 0; kh2 < 2; kh2++) {
            uint32_t ah[4][4];
            #pragma unroll
            for (int mi = 0; mi < 4; mi++) {
                uint32_t aaddr = st + (uint32_t)(wr*64 + mi*16 + rowA) * 80
                               + kh2*32 + kbyteA;
                LDSM4(ah[mi], aaddr);
            }
            #pragma unroll
            for (int np = 0; np < 2; np++) {
                uint32_t baddr = st + HSTG + (uint32_t)(wc*32 + np*16 + rowB) * 80
                               + kh2*32 + byteB;
                uint32_t bh4[4];
                LDSM4(bh4, baddr);
                #pragma unroll
                for (int mi = 0; mi < 4; mi++) {
                    MMA_F16(acc[mi][2*np],   ah[mi], bh4[0], bh4[1]);
                    MMA_F16(acc[mi][2*np+1], ah[mi], bh4[2], bh4[3]);
                }
            }
        }
    }

    // ---- fused epilogue: rmsnorm + rope + fp16 hi/lo emit (uniform shape) ----
    __syncthreads();
    float* red = (float*)smg;
    const int er = lane >> 2;
    const int ec = (lane & 3) * 2;
    const bool isq = (h < NH);
    const bool isv = (h >= NH + NKV);

    #pragma unroll
    for (int mi = 0; mi < 4; mi++) {
        float s0 = 0.f, s1 = 0.f;
        #pragma unroll
        for (int nn = 0; nn < 4; nn++) {
            s0 += acc[mi][nn][0]*acc[mi][nn][0] + acc[mi][nn][1]*acc[mi][nn][1];
            s1 += acc[mi][nn][2]*acc[mi][nn][2] + acc[mi][nn][3]*acc[mi][nn][3];
        }
        s0 += __shfl_xor_sync(0xffffffffu, s0, 1);
        s0 += __shfl_xor_sync(0xffffffffu, s0, 2);
        s1 += __shfl_xor_sync(0xffffffffu, s1, 1);
        s1 += __shfl_xor_sync(0xffffffffu, s1, 2);
        if ((lane & 3) == 0) {
            red[(wr*64 + mi*16 + er)     * 4 + wc] = s0;
            red[(wr*64 + mi*16 + er + 8) * 4 + wc] = s1;
        }
    }
    __syncthreads();

    const float* wn = isq ? qw : kw;
    const float fold = isq ? QSCALE : 1.0f;

    #pragma unroll
    for (int mi = 0; mi < 4; mi++) {
        #pragma unroll
        for (int half = 0; half < 2; half++) {
            const int row = wr*64 + mi*16 + er + half*8;
            const int n   = bm + row;
            const int b   = n >> 11;
            const int s   = n & 2047;
            float inv = 1.0f;
            if (!isv) {
                float ssq = red[row*4+0] + red[row*4+1] + red[row*4+2] + red[row*4+3];
                inv = rsqrtf(ssq * (1.0f / HD) + 1e-6f) * fold;
            }
            size_t drow;
            __half *dh, *dl;
            if (isq)      { drow = (size_t)(b*NH  + h)           * SS + s; dh = qh; dl = ql; }
            else if (!isv){ drow = (size_t)(b*NKV + h - NH)      * SS + s; dh = kh; dl = kl; }
            else          { drow = (size_t)(b*NKV + h - NH - NKV)* SS + s; dh = vh; dl = vl; }

            #pragma unroll
            for (int nn = 0; nn < 4; nn++) {
                const int col = wc*32 + nn*8 + ec;
                float v0 = acc[mi][nn][half*2];
                float v1 = acc[mi][nn][half*2+1];
                float o0, o1;
                if (!isv) {
                    float2 wv = *(const float2*)(wn + col);
                    float2 f  = *(const float2*)(freqs + (size_t)s*128 + col);
                    float x0 = v0 * inv * wv.x;
                    float x1 = v1 * inv * wv.y;
                    o0 = x0*f.x - x1*f.y;
                    o1 = x1*f.x + x0*f.y;
                } else {
                    o0 = v0; o1 = v1;
                }
                uint32_t hp = pack_h2(o0, o1);
                uint32_t lp = pack_h2(o0 - h2lo(hp), o1 - h2hi(hp));
                *(uint32_t*)(dh + drow*HD + col) = hp;
                *(uint32_t*)(dl + drow*HD + col) = lp;
            }
        }
    }
}

// ---------------- out-projection GEMM: fp16 2-pass (y exact-split, wo fp16) --
#define OSTG   10240
#define OSTAGE (3*OSTG)              // Ah, Al, Bh
#define OGSMEM (3*OSTAGE)            // 92160

__global__ void __launch_bounds__(256) gemm_out2(
    const __half* __restrict__ Ah, const __half* __restrict__ Al,
    const __half* __restrict__ Bh,
    float* __restrict__ C, int N, int K)
{
    extern __shared__ __align__(16) char smg[];
    const uint32_t sb = s2u(smg);
    const int tid  = threadIdx.x;
    const int lane = tid & 31;
    const int wid  = tid >> 5;
    const int wr   = wid >> 2;
    const int wc   = wid & 3;
    const int bm   = blockIdx.y << 7;
    const int bn   = blockIdx.x << 7;
    const int nk   = K >> 5;

    float acc[4][4][4];
    #pragma unroll
    for (int i = 0; i < 4; i++)
        #pragma unroll
        for (int j = 0; j < 4; j++)
            #pragma unroll
            for (int r = 0; r < 4; r++) acc[i][j][r] = 0.f;

    const int l8     = lane & 7;
    const int rowA   = ((lane >> 3) & 1) * 8 + l8;
    const int kbyteA = ((lane >> 4) & 1) * 16;
    const int rowB   = ((lane >> 4) & 1) * 8 + l8;
    const int byteB  = ((lane >> 3) & 1) * 16;

    auto fill = [&](int s, int kc) {
        const int k0 = kc << 5;
        const uint32_t dst = sb + s * OSTAGE;
        #pragma unroll
        for (int i = 0; i < 2; i++) {
            int lin = tid + i * 256;
            int row = lin >> 2;
            int ch  = lin & 3;
            uint32_t so = row * 80 + ch * 16;
            size_t ga = (size_t)(bm + row) * K + k0 + ch * 8;
            cp16(dst +          so, Ah + ga);
            cp16(dst + OSTG   + so, Al + ga);
            cp16(dst + 2*OSTG + so, Bh + (size_t)(bn + row) * K + k0 + ch * 8);
        }
        asm volatile("cp.async.commit_group;" ::: "memory");
    };

    fill(0, 0);
    if (nk > 1) fill(1, 1);

    for (int t = 0; t < nk; ++t) {
        if (t + 1 < nk) asm volatile("cp.async.wait_group 1;" ::: "memory");
        else            asm volatile("cp.async.wait_group 0;" ::: "memory");
        __syncthreads();

        if (t + 2 < nk) fill((t + 2) % 3, t + 2);

        const uint32_t st = sb + (t % 3) * OSTAGE;
        #pragma unroll
        for (int kh = 0; kh < 2; kh++) {
            uint32_t ah[4][4], al[4][4];
            #pragma unroll
            for (int mi = 0; mi < 4; mi++) {
                uint32_t aaddr = st + (uint32_t)(wr*64 + mi*16 + rowA) * 80
                               + kh*32 + kbyteA;
                LDSM4(ah[mi], aaddr);
                LDSM4(al[mi], aaddr + OSTG);
            }
            #pragma unroll
            for (int np = 0; np < 2; np++) {
                uint32_t baddr = st + 2*OSTG + (uint32_t)(wc*32 + np*16 + rowB) * 80
                               + kh*32 + byteB;
                uint32_t bh4[4];
                LDSM4(bh4, baddr);
                #pragma unroll
                for (int mi = 0; mi < 4; mi++) {
                    MMA_F16(acc[mi][2*np],   ah[mi], bh4[0], bh4[1]);
                    MMA_F16(acc[mi][2*np],   al[mi], bh4[0], bh4[1]);
                    MMA_F16(acc[mi][2*np+1], ah[mi], bh4[2], bh4[3]);
                    MMA_F16(acc[mi][2*np+1], al[mi], bh4[2], bh4[3]);
                }
            }
        }
    }

    const int er = lane >> 2;
    const int ec = (lane & 3) * 2;
    #pragma unroll
    for (int mi = 0; mi < 4; mi++) {
        #pragma unroll
        for (int nn = 0; nn < 4; nn++) {
            float* cp0 = C + (size_t)(bm + wr*64 + mi*16 + er) * N
                           + bn + wc*32 + nn*8 + ec;
            *(float2*)cp0         = make_float2(acc[mi][nn][0], acc[mi][nn][1]);
            *(float2*)(cp0 + 8*N) = make_float2(acc[mi][nn][2], acc[mi][nn][3]);
        }
    }
}

// ---------------- Flash attention (fp16 2-pass), BM=64, 4 warps --------------
#define FST 272
#define Q_OFF  0
#define QL_OFF (64*FST)
#define K_OFF  (2*64*FST)
#define V_OFF  (3*64*FST)
#define FLASH_SMEM (4*64*FST)           // 69632

__global__ void __launch_bounds__(128) flash_mma(
    const __half* __restrict__ qh, const __half* __restrict__ ql,
    const __half* __restrict__ kh, const __half* __restrict__ vh,
    __half* __restrict__ Yh, __half* __restrict__ Yl)
{
    extern __shared__ __align__(16) char smf[];
    const uint32_t sb = s2u(smf);
    const int tid  = threadIdx.x;
    const int lane = tid & 31;
    const int wid  = tid >> 5;
    const int qb   = gridDim.x - 1 - blockIdx.x;
    const int h    = blockIdx.y;
    const int b    = blockIdx.z;
    const int q0   = qb * 64;
    const int hkv  = h >> 2;
    const int mrow = wid * 16;

    const __half* qhp = qh + ((size_t)(b*NH  + h  ) * SS + q0) * HD;
    const __half* qlp = ql + ((size_t)(b*NH  + h  ) * SS + q0) * HD;
    const __half* khp = kh + ((size_t)(b*NKV + hkv) * SS) * HD;
    const __half* vhp = vh + ((size_t)(b*NKV + hkv) * SS) * HD;

    #pragma unroll
    for (int i = 0; i < 8; i++) {
        int lin = tid + i*128;
        int r   = lin >> 4;
        int ch  = lin & 15;
        cp16(sb + Q_OFF  + r*FST + ch*16, qhp + (size_t)r*HD + ch*8);
        cp16(sb + QL_OFF + r*FST + ch*16, qlp + (size_t)r*HD + ch*8);
    }
    asm volatile("cp.async.commit_group;" ::: "memory");

    const int l8 = lane & 7;
    const int rA = ((lane >> 3) & 1) * 8 + l8;
    const int cA = ((lane >> 4) & 1) * 16;
    const int rB = ((lane >> 4) & 1) * 8 + l8;
    const int cB = ((lane >> 3) & 1) * 16;
    const int lr = lane >> 2;
    const int l4 = lane & 3;

    float O[16][4];
    #pragma unroll
    for (int j = 0; j < 16; j++)
        #pragma unroll
        for (int r = 0; r < 4; r++) O[j][r] = 0.f;
    float m0v = -1e30f, m1v = -1e30f, l0v = 0.f, l1v = 0.f;

    const int nkb = qb + 1;
    for (int kb = 0; kb < nkb; ++kb) {
        const int k0 = kb * 64;
        if (kb) __syncthreads();
        #pragma unroll
        for (int i = 0; i < 8; i++) {
            int lin = tid + i*128;
            int r   = lin >> 4;
            int ch  = lin & 15;
            size_t g = (size_t)(k0 + r)*HD + ch*8;
            uint32_t so = r*FST + ch*16;
            cp16(sb + K_OFF + so, khp + g);
            cp16(sb + V_OFF + so, vhp + g);
        }
        asm volatile("cp.async.commit_group;" ::: "memory");
        asm volatile("cp.async.wait_group 0;" ::: "memory");
        __syncthreads();

        float S[8][4];
        #pragma unroll
        for (int j = 0; j < 8; j++)
            #pragma unroll
            for (int r = 0; r < 4; r++) S[j][r] = 0.f;

        #pragma unroll
        for (int kc = 0; kc < 8; kc++) {
            uint32_t qa_h[4], qa_l[4];
            uint32_t qaddr = sb + Q_OFF + (uint32_t)(mrow + rA)*FST + kc*32 + cA;
            LDSM4(qa_h, qaddr);
            LDSM4(qa_l, qaddr + QL_OFF);
            #pragma unroll
            for (int ng = 0; ng < 4; ng++) {
                uint32_t kaddr = sb + K_OFF + (uint32_t)(ng*16 + rB)*FST + kc*32 + cB;
                uint32_t bh4[4];
                LDSM4(bh4, kaddr);
                MMA_F16(S[2*ng],   qa_h, bh4[0], bh4[1]);
                MMA_F16(S[2*ng],   qa_l, bh4[0], bh4[1]);
                MMA_F16(S[2*ng+1], qa_h, bh4[2], bh4[3]);
                MMA_F16(S[2*ng+1], qa_l, bh4[2], bh4[3]);
            }
        }

        if (kb == qb) {
            int row0 = q0 + mrow + lr;
            int row1 = row0 + 8;
            #pragma unroll
            for (int j = 0; j < 8; j++) {
                int c0 = k0 + 8*j + 2*l4;
                if (c0     > row0) S[j][0] = -1e30f;
                if (c0 + 1 > row0) S[j][1] = -1e30f;
                if (c0     > row1) S[j][2] = -1e30f;
                if (c0 + 1 > row1) S[j][3] = -1e30f;
            }
        }

        {
            float mx = -1e30f;
            #pragma unroll
            for (int j = 0; j < 8; j++) mx = fmaxf(mx, fmaxf(S[j][0], S[j][1]));
            mx = fmaxf(mx, __shfl_xor_sync(0xffffffffu, mx, 1));
            mx = fmaxf(mx, __shfl_xor_sync(0xffffffffu, mx, 2));
            float mn = fmaxf(m0v, mx);
            float corr = ex2f(m0v - mn);
            m0v = mn;
            float rs = 0.f;
            #pragma unroll
            for (int j = 0; j < 8; j++) {
                S[j][0] = ex2f(S[j][0] - mn);
                S[j][1] = ex2f(S[j][1] - mn);
                rs += S[j][0] + S[j][1];
            }
            rs += __shfl_xor_sync(0xffffffffu, rs, 1);
            rs += __shfl_xor_sync(0xffffffffu, rs, 2);
            l0v = l0v * corr + rs;
            #pragma unroll
            for (int j = 0; j < 16; j++) { O[j][0] *= corr; O[j][1] *= corr; }
        }
        {
            float mx = -1e30f;
            #pragma unroll
            for (int j = 0; j < 8; j++) mx = fmaxf(mx, fmaxf(S[j][2], S[j][3]));
            mx = fmaxf(mx, __shfl_xor_sync(0xffffffffu, mx, 1));
            mx = fmaxf(mx, __shfl_xor_sync(0xffffffffu, mx, 2));
            float mn = fmaxf(m1v, mx);
            float corr = ex2f(m1v - mn);
            m1v = mn;
            float rs = 0.f;
            #pragma unroll
            for (int j = 0; j < 8; j++) {
                S[j][2] = ex2f(S[j][2] - mn);
                S[j][3] = ex2f(S[j][3] - mn);
                rs += S[j][2] + S[j][3];
            }
            rs += __shfl_xor_sync(0xffffffffu, rs, 1);
            rs += __shfl_xor_sync(0xffffffffu, rs, 2);
            l1v = l1v * corr + rs;
            #pragma unroll
            for (int j = 0; j < 16; j++) { O[j][2] *= corr; O[j][3] *= corr; }
        }

        // ---- O += P V (P exact fp16 hi/lo split; V single fp16) ----
        #pragma unroll
        for (int t = 0; t < 4; t++) {
            uint32_t Ahf[4], Alf[4];
            Ahf[0] = pack_h2(S[2*t][0],   S[2*t][1]);
            Ahf[1] = pack_h2(S[2*t][2],   S[2*t][3]);
            Ahf[2] = pack_h2(S[2*t+1][0], S[2*t+1][1]);
            Ahf[3] = pack_h2(S[2*t+1][2], S[2*t+1][3]);
            Alf[0] = pack_h2(S[2*t][0]   - h2lo(Ahf[0]), S[2*t][1]   - h2hi(Ahf[0]));
            Alf[1] = pack_h2(S[2*t][2]   - h2lo(Ahf[1]), S[2*t][3]   - h2hi(Ahf[1]));
            Alf[2] = pack_h2(S[2*t+1][0] - h2lo(Ahf[2]), S[2*t+1][1] - h2hi(Ahf[2]));
            Alf[3] = pack_h2(S[2*t+1][2] - h2lo(Ahf[3]), S[2*t+1][3] - h2hi(Ahf[3]));
            #pragma unroll
            for (int dg = 0; dg < 8; dg++) {
                uint32_t vaddr = sb + V_OFF + (uint32_t)(t*16 + rA)*FST + dg*32 + cA;
                uint32_t vf[4];
                LDSM4T(vf, vaddr);
                MMA_F16(O[2*dg],   Ahf, vf[0], vf[1]);
                MMA_F16(O[2*dg],   Alf, vf[0], vf[1]);
                MMA_F16(O[2*dg+1], Ahf, vf[2], vf[3]);
                MMA_F16(O[2*dg+1], Alf, vf[2], vf[3]);
            }
        }
    }

    // ---- write O as fp16 hi + fp16 residual (feeds gemm_out2) ----
    float inv0 = 1.0f / l0v;
    float inv1 = 1.0f / l1v;
    int row0 = q0 + mrow + lr;
    size_t base0 = (size_t)(b*SS + row0) * DD + h*HD;
    size_t base1 = base0 + (size_t)8 * DD;
    #pragma unroll
    for (int j = 0; j < 16; j++) {
        float a0 = O[j][0]*inv0, a1 = O[j][1]*inv0;
        float b0 = O[j][2]*inv1, b1 = O[j][3]*inv1;
        uint32_t h0 = pack_h2(a0, a1);
        uint32_t l0 = pack_h2(a0 - h2lo(h0), a1 - h2hi(h0));
        uint32_t h1 = pack_h2(b0, b1);
        uint32_t l1 = pack_h2(b0 - h2lo(h1), b1 - h2hi(h1));
        *(uint32_t*)(Yh + base0 + 8*j + 2*l4) = h0;
        *(uint32_t*)(Yl + base0 + 8*j + 2*l4) = l0;
        *(uint32_t*)(Yh + base1 + 8*j + 2*l4) = h1;
        *(uint32_t*)(Yl + base1 + 8*j + 2*l4) = l1;
    }
}

// ---------------- launch ----------------------------------------------------
extern "C" void kernel_launch(void* const* d_in, const int* in_sizes, int n_in,
                              void* d_out, int out_size)
{
    const float* x     = (const float*)d_in[0];
    const float* freqs = (const float*)d_in[1];
    const float* wqkv  = (const float*)d_in[2];
    const float* wo    = (const float*)d_in[3];
    const float* qw    = (const float*)d_in[4];
    const float* kw    = (const float*)d_in[5];
    float* out = (float*)d_out;

    __half *p_xh, *p_wqh, *p_woh, *p_yh, *p_yl;
    __half *p_qh, *p_ql, *p_kh, *p_kl, *p_vh, *p_vl;
    cudaGetSymbolAddress((void**)&p_xh,  g_xh);
    cudaGetSymbolAddress((void**)&p_wqh, g_wqh);
    cudaGetSymbolAddress((void**)&p_woh, g_woh);
    cudaGetSymbolAddress((void**)&p_yh,  g_yh);
    cudaGetSymbolAddress((void**)&p_yl,  g_yl);
    cudaGetSymbolAddress((void**)&p_qh,  g_qh);
    cudaGetSymbolAddress((void**)&p_ql,  g_ql);
    cudaGetSymbolAddress((void**)&p_kh,  g_kh);
    cudaGetSymbolAddress((void**)&p_kl,  g_kl);
    cudaGetSymbolAddress((void**)&p_vh,  g_vh);
    cudaGetSymbolAddress((void**)&p_vl,  g_vl);

    cudaFuncSetAttribute(gemm_qkv,
                         cudaFuncAttributeMaxDynamicSharedMemorySize, HGSMEM);
    cudaFuncSetAttribute(gemm_out2,
                         cudaFuncAttributeMaxDynamicSharedMemorySize, OGSMEM);
    cudaFuncSetAttribute(flash_mma,
                         cudaFuncAttributeMaxDynamicSharedMemorySize, FLASH_SMEM);

    const int n4_x  = BB*SS*DD / 4;
    const int n4_wq = QKVE*DD  / 4;
    const int n4_wo = DD*DD    / 4;

    // 0) converts (all fp16 single)
    to_half<<<n4_x /256, 256>>>((const float4*)x,    (uint2*)p_xh,  n4_x);
    to_half<<<n4_wq/256, 256>>>((const float4*)wqkv, (uint2*)p_wqh, n4_wq);
    to_half<<<n4_wo/256, 256>>>((const float4*)wo,   (uint2*)p_woh, n4_wo);

    // 1) fused QKV projection + RMSNorm + RoPE (uniform hi/lo emit)
    gemm_qkv<<<dim3(EHEADS, (BB*SS)/128), 256, HGSMEM>>>(
        p_xh, p_wqh, freqs, qw, kw,
        p_qh, p_ql, p_kh, p_kl, p_vh, p_vl);

    // 2) Flash attention (fp16 2-pass); writes y as fp16 hi/lo (exact split)
    flash_mma<<<dim3(SS/64, NH, BB), 128, FLASH_SMEM>>>(
        p_qh, p_ql, p_kh, p_vh, p_yh, p_yl);

    // 3) Output projection (fp16 2-pass: y exact, wo quantized)
    gemm_out2<<<dim3(DD/128, (BB*SS)/128), 256, OGSMEM>>>(
        p_yh, p_yl, p_woh, out, DD, NH*HD);
}